// round 12
// baseline (speedup 1.0000x reference)
#include <cuda_runtime.h>
#include <cuda_fp16.h>
#include <stdint.h>

#define B_ 4
#define C_ 256
#define N_ 4096

// ---------------- device scratch (swizzled tile layouts, attn-ready) --------
__device__ __align__(256) __half g_qt [(size_t)B_ * 64 * 4096]; // 8KB q-tiles [r][qh32|ql32] sw128
__device__ __align__(256) __half g_kt [(size_t)B_ * 64 * 4096]; // 8KB k-tiles
__device__ __align__(256) __half g_vt [(size_t)B_ * 64 * 16384];// 32KB V^T tiles [c][n] sw128

// ---------------- asm helpers ----------------
__device__ __forceinline__ uint32_t smem_u32(const void* p) {
    uint32_t a;
    asm("{ .reg .u64 t; cvta.to.shared.u64 t, %1; cvt.u32.u64 %0, t; }" : "=r"(a) : "l"(p));
    return a;
}
__device__ __forceinline__ void ldsm4(uint32_t* r, uint32_t a) {
    asm volatile("ldmatrix.sync.aligned.m8n8.x4.shared.b16 {%0,%1,%2,%3}, [%4];"
        : "=r"(r[0]), "=r"(r[1]), "=r"(r[2]), "=r"(r[3]) : "r"(a));
}
__device__ __forceinline__ void mma16816(float* c, const uint32_t* a, const uint32_t* b) {
    asm volatile("mma.sync.aligned.m16n8k16.row.col.f32.f16.f16.f32 "
        "{%0,%1,%2,%3}, {%4,%5,%6,%7}, {%8,%9}, {%0,%1,%2,%3};"
        : "+f"(c[0]), "+f"(c[1]), "+f"(c[2]), "+f"(c[3])
        : "r"(a[0]), "r"(a[1]), "r"(a[2]), "r"(a[3]), "r"(b[0]), "r"(b[1]));
}
__device__ __forceinline__ uint32_t pk(float lo, float hi) {
    uint32_t r;
    asm("cvt.rn.f16x2.f32 %0, %1, %2;" : "=r"(r) : "f"(hi), "f"(lo));
    return r;
}
#define MBAR_INIT(m, c) \
    asm volatile("mbarrier.init.shared.b64 [%0], %1;" :: "r"((uint32_t)(m)), "r"((uint32_t)(c)) : "memory")
#define MBAR_EXPECT_TX(m, b) \
    asm volatile("mbarrier.arrive.expect_tx.shared.b64 _, [%0], %1;" :: "r"((uint32_t)(m)), "r"((uint32_t)(b)) : "memory")
#define MBAR_WAIT(m, ph) do { \
    uint32_t _m = (uint32_t)(m), _p = (uint32_t)(ph), _d; \
    asm volatile("{\n\t.reg .pred p;\n\t" \
        "mbarrier.try_wait.parity.acquire.cta.shared::cta.b64 p, [%1], %2;\n\tselp.b32 %0,1,0,p;\n\t}" \
        : "=r"(_d) : "r"(_m), "r"(_p) : "memory"); \
    if (!_d) { asm volatile("{\n\t.reg .pred P1;\n\tWL_%=:\n\t" \
        "mbarrier.try_wait.parity.acquire.cta.shared::cta.b64 P1, [%0], %1, 0x989680;\n\t" \
        "@P1 bra.uni WD_%=;\n\tbra.uni WL_%=;\n\tWD_%=:\n\t}" :: "r"(_m), "r"(_p) : "memory"); } \
} while (0)
__device__ __forceinline__ void bulk_g2s(uint32_t dst, const void* src, uint32_t bytes, uint32_t mbar) {
    asm volatile("cp.async.bulk.shared::cluster.global.mbarrier::complete_tx::bytes [%0], [%1], %2, [%3];"
        :: "r"(dst), "l"(__cvta_generic_to_global(src)), "r"(bytes), "r"(mbar) : "memory");
}
#define NBAR_SYNC(id, cnt)   asm volatile("bar.sync %0, %1;"   :: "r"(id), "r"(cnt) : "memory")
#define NBAR_ARRIVE(id, cnt) asm volatile("bar.arrive %0, %1;" :: "r"(id), "r"(cnt) : "memory")

// ---------------------------------------------------------------------------
// Kernel 1: HMMA projection (unchanged from R9 — passed, rel 5.7e-5).
// ---------------------------------------------------------------------------
#define PJ_WH  0
#define PJ_WL  8192
#define PJ_X32 16384
#define PJ_XH  33792
#define PJ_XL  43008
#define PJ_SZ  52224

__global__ __launch_bounds__(256, 2) void proj_kernel(
    const float* __restrict__ x, const float* __restrict__ wv,
    const float* __restrict__ wq, const float* __restrict__ wk)
{
    extern __shared__ char smc[];
    float* xs32 = (float*)(smc + PJ_X32);
    const uint32_t sb = smem_u32(smc);
    const int tid = threadIdx.x, w = tid >> 5, lane = tid & 31;
    const int wn = w & 3, wj = w >> 2;
    const int b = blockIdx.z, n0 = blockIdx.x * 64, jt = blockIdx.y;
    const bool isQK = (jt == 4);

    float acc[4][4];
#pragma unroll
    for (int i = 0; i < 4; i++)
#pragma unroll
        for (int j = 0; j < 4; j++) acc[i][j] = 0.f;

    for (int c0 = 0; c0 < 256; c0 += 64) {
        __syncthreads();
#pragma unroll
        for (int it = 0; it < 4; it++) {
            int f4 = tid + it * 256;
            int jl = f4 >> 4, c4 = f4 & 15;
            const float* src;
            if (!isQK) src = wv + (size_t)(jt * 64 + jl) * 256 + c0 + c4 * 4;
            else src = ((jl < 32) ? (wq + (size_t)jl * 256) : (wk + (size_t)(jl - 32) * 256)) + c0 + c4 * 4;
            float4 v = *(const float4*)src;
            __half h[4];
            h[0] = __float2half_rn(v.x); h[1] = __float2half_rn(v.y);
            h[2] = __float2half_rn(v.z); h[3] = __float2half_rn(v.w);
            *(uint2*)(smc + PJ_WH + jl * 128 + ((c4 * 8) ^ ((jl & 7) << 4))) = *(uint2*)h;
            if (isQK) {
                __half l[4];
                l[0] = __float2half_rn(v.x - __half2float(h[0]));
                l[1] = __float2half_rn(v.y - __half2float(h[1]));
                l[2] = __float2half_rn(v.z - __half2float(h[2]));
                l[3] = __float2half_rn(v.w - __half2float(h[3]));
                *(uint2*)(smc + PJ_WL + jl * 128 + ((c4 * 8) ^ ((jl & 7) << 4))) = *(uint2*)l;
            }
        }
#pragma unroll
        for (int it = 0; it < 4; it++) {
            int f4 = tid + it * 256;
            int cl = f4 >> 4, n4 = f4 & 15;
            float4 v = *(const float4*)(x + (size_t)(b * 256 + c0 + cl) * 4096 + n0 + n4 * 4);
            *(float4*)(xs32 + cl * 68 + n4 * 4) = v;
        }
        __syncthreads();
        {
            int n = tid & 63, cq = tid >> 6;
#pragma unroll
            for (int i = 0; i < 4; i++) {
                int c = cq * 16 + i * 4;
                __half h[4], l[4];
#pragma unroll
                for (int k2 = 0; k2 < 4; k2++) {
                    float f = xs32[(c + k2) * 68 + n];
                    h[k2] = __float2half_rn(f);
                    l[k2] = __float2half_rn(f - __half2float(h[k2]));
                }
                *(uint2*)(smc + PJ_XH + n * 144 + c * 2) = *(uint2*)h;
                *(uint2*)(smc + PJ_XL + n * 144 + c * 2) = *(uint2*)l;
            }
        }
        __syncthreads();
#pragma unroll
        for (int kk = 0; kk < 4; kk++) {
            uint32_t ah[4], al[4];
            int arow = wn * 16 + (lane & 7) + ((lane & 8) ? 8 : 0);
            int aoff = arow * 144 + kk * 32 + ((lane & 16) ? 16 : 0);
            ldsm4(ah, sb + PJ_XH + aoff);
            ldsm4(al, sb + PJ_XL + aoff);
            int jr0 = wj * 32 + (lane & 7) + ((lane & 16) ? 8 : 0);
            int bcol = kk * 32 + ((lane & 8) ? 16 : 0);
#pragma unroll
            for (int nt2 = 0; nt2 < 2; nt2++) {
                int jrow = jr0 + nt2 * 16;
                uint32_t bh[4];
                ldsm4(bh, sb + PJ_WH + jrow * 128 + (bcol ^ ((jrow & 7) << 4)));
                mma16816(acc[nt2*2],   ah, bh);
                mma16816(acc[nt2*2+1], ah, bh + 2);
                mma16816(acc[nt2*2],   al, bh);
                mma16816(acc[nt2*2+1], al, bh + 2);
                if (isQK) {
                    uint32_t bl[4];
                    ldsm4(bl, sb + PJ_WL + jrow * 128 + (bcol ^ ((jrow & 7) << 4)));
                    mma16816(acc[nt2*2],   ah, bl);
                    mma16816(acc[nt2*2+1], ah, bl + 2);
                }
            }
        }
    }

    const int rA = wn * 16 + (lane >> 2), rB = rA + 8;
    if (isQK) {
#pragma unroll
        for (int t = 0; t < 4; t++) {
            int j = wj * 32 + (t >> 1) * 16 + (t & 1) * 8 + 2 * (lane & 3);
            bool isQ = j < 32;
            int qc = isQ ? j : j - 32;
            char* tb = (char*)((isQ ? g_qt : g_kt) + ((size_t)(b * 64 + blockIdx.x)) * 4096);
#pragma unroll
            for (int rr = 0; rr < 2; rr++) {
                int r = rr ? rB : rA;
                float v0 = acc[t][rr * 2], v1 = acc[t][rr * 2 + 1];
                __half h0 = __float2half_rn(v0), h1 = __float2half_rn(v1);
                __half l0 = __float2half_rn(v0 - __half2float(h0));
                __half l1 = __float2half_rn(v1 - __half2float(h1));
                uint32_t hp = (uint32_t)*(uint16_t*)&h0 | ((uint32_t)*(uint16_t*)&h1 << 16);
                uint32_t lp = (uint32_t)*(uint16_t*)&l0 | ((uint32_t)*(uint16_t*)&l1 << 16);
                *(uint32_t*)(tb + r * 128 + ((qc * 2)      ^ ((r & 7) << 4))) = hp;
                *(uint32_t*)(tb + r * 128 + ((64 + qc * 2) ^ ((r & 7) << 4))) = lp;
            }
        }
    } else {
        __syncthreads();
        __half* st = (__half*)(smc + PJ_XH);
#pragma unroll
        for (int t = 0; t < 4; t++) {
            int j = wj * 32 + (t >> 1) * 16 + (t & 1) * 8 + 2 * (lane & 3);
            st[j * 72 + rA]       = __float2half_rn(acc[t][0]);
            st[(j + 1) * 72 + rA] = __float2half_rn(acc[t][1]);
            st[j * 72 + rB]       = __float2half_rn(acc[t][2]);
            st[(j + 1) * 72 + rB] = __float2half_rn(acc[t][3]);
        }
        __syncthreads();
        char* tb = (char*)(g_vt + ((size_t)(b * 64 + blockIdx.x)) * 16384);
        int jl = tid >> 2, n8 = tid & 3;
        int c = jt * 64 + jl;
#pragma unroll
        for (int hh = 0; hh < 2; hh++) {
            int nl = n8 * 16 + hh * 8;
            uint4 v = *(uint4*)(smc + PJ_XH + (jl * 72 + nl) * 2);
            *(uint4*)(tb + c * 128 + ((nl * 2) ^ ((c & 7) << 4))) = v;
        }
    }
}

// ---------------------------------------------------------------------------
// Kernel 2: warp-specialized HMMA flash attention, 3-slot P pipeline.
// G1 (w 0-3): GEMM1+softmax -> P/sc slots (t%3); K pipeline.
// G2 (w 4-7): rescale + GEMM2; V pipeline.
// Named bars: 1 G1-internal(128), 14 G2-internal(128),
//   ready[s] = 2+s (G1 arrive / G2 sync, 256), free[s] = 8+s (G2 arrive / G1 sync, 256),
//   6,7 epilogue rendezvous (256).
// ---------------------------------------------------------------------------
#define NSLOT   3
#define OFF_P   0          /* 3 x 4608 = 13824 (slot0 head doubles as 4KB Q staging) */
#define OFF_SC  13824      /* 3 x 128 */
#define OFF_MX  14208      /* 2 x 256 */
#define OFF_LS  14720      /* 256 */
#define OFF_RDT 14976      /* 16384 */
#define OFF_K   31360      /* 2 x 8192 */
#define OFF_V   47744      /* 2 x 32768 */
#define OFF_BAR 113280
#define SMEM_SZ 113344

__global__ __launch_bounds__(256, 2) void attn_kernel(
    const float* __restrict__ x, const float* __restrict__ gamma,
    const float* __restrict__ beta, const float* __restrict__ mean,
    const float* __restrict__ var, float* __restrict__ out)
{
    extern __shared__ char smc[];
    float* rdt = (float*)(smc + OFF_RDT);
    float* ls  = (float*)(smc + OFF_LS);
    const uint32_t sb = smem_u32(smc);
    const uint32_t barK0 = sb + OFF_BAR, barK1 = sb + OFF_BAR + 8;
    const uint32_t barV0 = sb + OFF_BAR + 16, barV1 = sb + OFF_BAR + 24;
    const int tid = threadIdx.x, w = tid >> 5, lane = tid & 31;
    const int b = blockIdx.y, qt = blockIdx.x, qb = qt * 32;

    for (int i = tid; i < 4096; i += 256) {
        int dy = i >> 6, dx = i & 63;
        rdt[i] = 1.0f / (sqrtf((float)(dy * dy + dx * dx)) + 1.0f);
    }
    if (tid == 0) {
        MBAR_INIT(barK0, 1); MBAR_INIT(barK1, 1);
        MBAR_INIT(barV0, 1); MBAR_INIT(barV1, 1);
    }
    {   // Q staging into P slot0 head (4KB); consumed into regs before t=0 writes
        const char* qsrc = (const char*)(g_qt + ((size_t)(b * 64 + (qt >> 1))) * 4096)
                         + (size_t)(qt & 1) * 32 * 128;
        ((uint4*)smc)[tid] = ((const uint4*)qsrc)[tid];
    }
    __syncthreads();

    const __half* kt = g_kt + (size_t)b * 64 * 4096;
    const __half* vt = g_vt + (size_t)b * 64 * 16384;
    if (tid == 0) {   // prologue: K(0),K(1),V(0),V(1)
        MBAR_EXPECT_TX(barK0, 8192);  bulk_g2s(sb + OFF_K, kt, 8192, barK0);
        MBAR_EXPECT_TX(barK1, 8192);  bulk_g2s(sb + OFF_K + 8192, kt + 4096, 8192, barK1);
        MBAR_EXPECT_TX(barV0, 32768); bulk_g2s(sb + OFF_V, vt, 32768, barV0);
        MBAR_EXPECT_TX(barV1, 32768); bulk_g2s(sb + OFF_V + 32768, vt + 16384, 32768, barV1);
    }

    if (w < 4) {
        // ================= G1: GEMM1 + softmax =================
        const int wm = w & 1, wc = w >> 1;
        const int rxA = wm * 16 + (lane >> 2), rxB = rxA + 8;
        const int c0 = 2 * (lane & 3);
        const int rxAi = (qt & 1) * 32 + rxA, rxBi = rxAi + 8;
        const int ry = qt >> 1;

        uint32_t qf[2][2][4];
#pragma unroll
        for (int hl = 0; hl < 2; hl++)
#pragma unroll
            for (int kk = 0; kk < 2; kk++) {
                int row = wm * 16 + (lane & 7) + ((lane & 8) ? 8 : 0);
                int colb = hl * 64 + kk * 32 + ((lane & 16) ? 16 : 0);
                ldsm4(qf[hl][kk], sb + row * 128 + (colb ^ ((row & 7) << 4)));
            }
        NBAR_SYNC(1, 128);   // all G1 qf reads done before P slot0 writes at t=0

        float mA = -1e30f, mB = -1e30f, lA = 0.f, lB = 0.f;

        for (int t = 0; t < 64; t++) {
            MBAR_WAIT(((t & 1) ? barK1 : barK0), (t >> 1) & 1);
            const uint32_t bK = sb + OFF_K + (t & 1) * 8192;

            float s[4][4];
#pragma unroll
            for (int i = 0; i < 4; i++)
#pragma unroll
                for (int j = 0; j < 4; j++) s[i][j] = 0.f;
#pragma unroll
            for (int kk = 0; kk < 2; kk++) {
                int colb = kk * 32 + ((lane & 8) ? 16 : 0);
                int kr0 = wc * 32 + (lane & 7) + ((lane & 16) ? 8 : 0);
                uint32_t bh0[4], bh1[4], bl0[4], bl1[4];
                ldsm4(bh0, bK + kr0 * 128 + (colb ^ ((kr0 & 7) << 4)));
                ldsm4(bl0, bK + kr0 * 128 + ((colb + 64) ^ ((kr0 & 7) << 4)));
                int kr1 = kr0 + 16;
                ldsm4(bh1, bK + kr1 * 128 + (colb ^ ((kr1 & 7) << 4)));
                ldsm4(bl1, bK + kr1 * 128 + ((colb + 64) ^ ((kr1 & 7) << 4)));
                mma16816(s[0], qf[0][kk], bh0);
                mma16816(s[1], qf[0][kk], bh0 + 2);
                mma16816(s[2], qf[0][kk], bh1);
                mma16816(s[3], qf[0][kk], bh1 + 2);
                mma16816(s[0], qf[1][kk], bh0);
                mma16816(s[1], qf[1][kk], bh0 + 2);
                mma16816(s[2], qf[1][kk], bh1);
                mma16816(s[3], qf[1][kk], bh1 + 2);
                mma16816(s[0], qf[0][kk], bl0);
                mma16816(s[1], qf[0][kk], bl0 + 2);
                mma16816(s[2], qf[0][kk], bl1);
                mma16816(s[3], qf[0][kk], bl1 + 2);
            }

            const float* rdtp = rdt + ((ry > t) ? (ry - t) : (t - ry)) * 64;
            float tmA = -1e30f, tmB = -1e30f;
#pragma unroll
            for (int idx = 0; idx < 4; idx++) {
                int c = wc * 32 + (idx >> 1) * 16 + (idx & 1) * 8 + c0;
                int d0 = rxAi - c;     d0 = d0 < 0 ? -d0 : d0;
                int d1 = rxAi - c - 1; d1 = d1 < 0 ? -d1 : d1;
                int d2 = rxBi - c;     d2 = d2 < 0 ? -d2 : d2;
                int d3 = rxBi - c - 1; d3 = d3 < 0 ? -d3 : d3;
                s[idx][0] *= rdtp[d0];
                s[idx][1] *= rdtp[d1];
                s[idx][2] *= rdtp[d2];
                s[idx][3] *= rdtp[d3];
                tmA = fmaxf(tmA, fmaxf(s[idx][0], s[idx][1]));
                tmB = fmaxf(tmB, fmaxf(s[idx][2], s[idx][3]));
            }
            tmA = fmaxf(tmA, __shfl_xor_sync(0xffffffffu, tmA, 1));
            tmA = fmaxf(tmA, __shfl_xor_sync(0xffffffffu, tmA, 2));
            tmB = fmaxf(tmB, __shfl_xor_sync(0xffffffffu, tmB, 1));
            tmB = fmaxf(tmB, __shfl_xor_sync(0xffffffffu, tmB, 2));
            float* mxs = (float*)(smc + OFF_MX + (t & 1) * 256);
            if ((lane & 3) == 0) {
                mxs[wc * 32 + rxA] = tmA;
                mxs[wc * 32 + rxB] = tmB;
            }
            NBAR_SYNC(1, 128);
            if (tid == 0 && t + 2 < 64) {
                uint32_t bk = (t & 1) ? barK1 : barK0;
                MBAR_EXPECT_TX(bk, 8192);
                bulk_g2s(sb + OFF_K + (t & 1) * 8192, kt + (size_t)(t + 2) * 4096, 8192, bk);
            }
            float gmA = fmaxf(mxs[rxA], mxs[32 + rxA]);
            float gmB = fmaxf(mxs[rxB], mxs[32 + rxB]);
            float mnA = fmaxf(mA, gmA), mnB = fmaxf(mB, gmB);
            float scA = __expf(mA - mnA), scB = __expf(mB - mnB);
            mA = mnA; mB = mnB;

            float sumA = 0.f, sumB = 0.f;
            uint32_t pp[4][2];
#pragma unroll
            for (int idx = 0; idx < 4; idx++) {
                float p0 = __expf(s[idx][0] - mnA), p1 = __expf(s[idx][1] - mnA);
                float p2 = __expf(s[idx][2] - mnB), p3 = __expf(s[idx][3] - mnB);
                sumA += p0 + p1; sumB += p2 + p3;
                pp[idx][0] = pk(p0, p1);
                pp[idx][1] = pk(p2, p3);
            }
            sumA += __shfl_xor_sync(0xffffffffu, sumA, 1);
            sumA += __shfl_xor_sync(0xffffffffu, sumA, 2);
            sumB += __shfl_xor_sync(0xffffffffu, sumB, 1);
            sumB += __shfl_xor_sync(0xffffffffu, sumB, 2);
            lA = lA * scA + sumA;
            lB = lB * scB + sumB;

            const int sl = t % NSLOT;
            if (t >= NSLOT) NBAR_SYNC(8 + sl, 256);   // slot free (G2 done t-3)
            char* Pb = smc + OFF_P + sl * 4608;
#pragma unroll
            for (int idx = 0; idx < 4; idx++) {
                int c = wc * 32 + (idx >> 1) * 16 + (idx & 1) * 8 + c0;
                *(uint32_t*)(Pb + (rxA * 72 + c) * 2) = pp[idx][0];
                *(uint32_t*)(Pb + (rxB * 72 + c) * 2) = pp[idx][1];
            }
            if (wc == 0 && (lane & 3) == 0) {
                float* scb = (float*)(smc + OFF_SC + sl * 128);
                scb[rxA] = scA;
                scb[rxB] = scB;
            }
            NBAR_ARRIVE(2 + sl, 256);                 // P(t) ready
        }
        if ((lane & 3) == 0) {
            ls[wc * 32 + rxA] = lA;
            ls[wc * 32 + rxB] = lB;
        }
        NBAR_SYNC(6, 256);   // ls visible to G2
        NBAR_SYNC(7, 256);   // G2's Ys writes done
    } else {
        // ================= G2: rescale + GEMM2 =================
        const int wq2 = w - 4;
        const int c0 = 2 * (lane & 3);
        const int r0 = lane >> 2;

        float y[2][8][4];
#pragma unroll
        for (int bd = 0; bd < 2; bd++)
#pragma unroll
            for (int i = 0; i < 8; i++)
#pragma unroll
                for (int j = 0; j < 4; j++) y[bd][i][j] = 0.f;

        for (int t = 0; t < 64; t++) {
            const int sl = t % NSLOT;
            NBAR_SYNC(2 + sl, 256);           // P(t), sc(t) ready
            const float* scb = (const float*)(smc + OFF_SC + sl * 128);
            float s0 = scb[r0], s1 = scb[r0 + 8], s2 = scb[r0 + 16], s3 = scb[r0 + 24];
            bool nor = (s0 == 1.f) & (s1 == 1.f) & (s2 == 1.f) & (s3 == 1.f);
            if (!__all_sync(0xffffffffu, nor)) {
#pragma unroll
                for (int i = 0; i < 8; i++) {
                    y[0][i][0] *= s0; y[0][i][1] *= s0;
                    y[0][i][2] *= s1; y[0][i][3] *= s1;
                    y[1][i][0] *= s2; y[1][i][1] *= s2;
                    y[1][i][2] *= s3; y[1][i][3] *= s3;
                }
            }
            MBAR_WAIT(((t & 1) ? barV1 : barV0), (t >> 1) & 1);
            const uint32_t bV = sb + OFF_V + (t & 1) * 32768;
            const uint32_t Pb = sb + OFF_P + sl * 4608;
#pragma unroll
            for (int kk = 0; kk < 4; kk++) {
                uint32_t pa0[4], pa1[4];
                int pr = (lane & 7) + ((lane & 8) ? 8 : 0);
                int pc = kk * 16 + ((lane & 16) ? 8 : 0);
                ldsm4(pa0, Pb + (pr * 72 + pc) * 2);
                ldsm4(pa1, Pb + ((pr + 16) * 72 + pc) * 2);
                int colb = kk * 32 + ((lane & 8) ? 16 : 0);
#pragma unroll
                for (int np = 0; np < 4; np++) {
                    int vrow = wq2 * 64 + np * 16 + (lane & 7) + ((lane & 16) ? 8 : 0);
                    uint32_t bv[4];
                    ldsm4(bv, bV + vrow * 128 + (colb ^ ((vrow & 7) << 4)));
                    mma16816(y[0][np*2],   pa0, bv);
                    mma16816(y[0][np*2+1], pa0, bv + 2);
                    mma16816(y[1][np*2],   pa1, bv);
                    mma16816(y[1][np*2+1], pa1, bv + 2);
                }
            }
            NBAR_SYNC(14, 128);               // all G2 done with V(t)/P(t)
            if (tid == 128 && t + 2 < 64) {
                uint32_t bv2 = (t & 1) ? barV1 : barV0;
                MBAR_EXPECT_TX(bv2, 32768);
                bulk_g2s(sb + OFF_V + (t & 1) * 32768, vt + (size_t)(t + 2) * 16384, 32768, bv2);
            }
            if (t + NSLOT < 64) NBAR_ARRIVE(8 + sl, 256);   // P slot free
        }

        NBAR_SYNC(6, 256);   // ls visible
        float rl[4];
#pragma unroll
        for (int q = 0; q < 4; q++) {
            int r = r0 + q * 8;
            rl[q] = 1.f / (ls[r] + ls[32 + r]);
        }
        NBAR_SYNC(14, 128);  // all G2 read ls before Ys overwrite
        float* Ys = (float*)smc;   // [32][260] f32 (overlaps P/sc/mx/ls/rdt — all dead)
#pragma unroll
        for (int bd = 0; bd < 2; bd++)
#pragma unroll
            for (int nt = 0; nt < 8; nt++) {
                int c = wq2 * 64 + (nt >> 1) * 16 + (nt & 1) * 8 + c0;
                int rA = bd * 16 + r0, rB = rA + 8;
                Ys[rA * 260 + c]     = y[bd][nt][0] * rl[bd * 2];
                Ys[rA * 260 + c + 1] = y[bd][nt][1] * rl[bd * 2];
                Ys[rB * 260 + c]     = y[bd][nt][2] * rl[bd * 2 + 1];
                Ys[rB * 260 + c + 1] = y[bd][nt][3] * rl[bd * 2 + 1];
            }
        NBAR_SYNC(7, 256);   // Ys published
    }

    // ---- common epilogue: BN + ReLU + residual (Ys visible after bar 7)
    float* Ys = (float*)smc;
    const int n = tid & 31, cg = tid >> 5;
#pragma unroll 4
    for (int it = 0; it < 32; it++) {
        int c = it * 8 + cg;
        float inv = gamma[c] * rsqrtf(var[c] + 1e-5f);
        float add = fmaf(-mean[c], inv, beta[c]);
        size_t idx = ((size_t)b * C_ + c) * N_ + qb + n;
        float yv = Ys[n * 260 + c];
        out[idx] = fmaxf(fmaf(yv, inv, add), 0.f) + x[idx];
    }
}

// ---------------------------------------------------------------------------
extern "C" void kernel_launch(void* const* d_in, const int* in_sizes, int n_in,
                              void* d_out, int out_size)
{
    (void)in_sizes; (void)n_in; (void)out_size;
    const float* x     = (const float*)d_in[0];
    const float* wv    = (const float*)d_in[1];
    const float* wq    = (const float*)d_in[2];
    const float* wk    = (const float*)d_in[3];
    const float* gamma = (const float*)d_in[4];
    const float* beta  = (const float*)d_in[5];
    const float* mean  = (const float*)d_in[6];
    const float* var   = (const float*)d_in[7];
    float* out = (float*)d_out;

    cudaFuncSetAttribute(proj_kernel, cudaFuncAttributeMaxDynamicSharedMemorySize, PJ_SZ);
    proj_kernel<<<dim3(64, 5, B_), 256, PJ_SZ>>>(x, wv, wq, wk);
    cudaFuncSetAttribute(attn_kernel, cudaFuncAttributeMaxDynamicSharedMemorySize, SMEM_SZ);
    attn_kernel<<<dim3(128, B_), 256, SMEM_SZ>>>(x, gamma, beta, mean, var, out);
}

// round 13
// speedup vs baseline: 1.0160x; 1.0160x over previous
#include <cuda_runtime.h>
#include <cuda_fp16.h>
#include <stdint.h>

#define B_ 4
#define C_ 256
#define N_ 4096

// ---------------- device scratch (swizzled tile layouts, attn-ready) --------
__device__ __align__(256) __half g_qt [(size_t)B_ * 64 * 4096]; // 8KB q-tiles [r][qh32|ql32] sw128
__device__ __align__(256) __half g_kt [(size_t)B_ * 64 * 4096]; // 8KB k-tiles
__device__ __align__(256) __half g_vt [(size_t)B_ * 64 * 16384];// 32KB V^T tiles [c][n] sw128

// ---------------- asm helpers ----------------
__device__ __forceinline__ uint32_t smem_u32(const void* p) {
    uint32_t a;
    asm("{ .reg .u64 t; cvta.to.shared.u64 t, %1; cvt.u32.u64 %0, t; }" : "=r"(a) : "l"(p));
    return a;
}
__device__ __forceinline__ void ldsm4(uint32_t* r, uint32_t a) {
    asm volatile("ldmatrix.sync.aligned.m8n8.x4.shared.b16 {%0,%1,%2,%3}, [%4];"
        : "=r"(r[0]), "=r"(r[1]), "=r"(r[2]), "=r"(r[3]) : "r"(a));
}
__device__ __forceinline__ void mma16816(float* c, const uint32_t* a, const uint32_t* b) {
    asm volatile("mma.sync.aligned.m16n8k16.row.col.f32.f16.f16.f32 "
        "{%0,%1,%2,%3}, {%4,%5,%6,%7}, {%8,%9}, {%0,%1,%2,%3};"
        : "+f"(c[0]), "+f"(c[1]), "+f"(c[2]), "+f"(c[3])
        : "r"(a[0]), "r"(a[1]), "r"(a[2]), "r"(a[3]), "r"(b[0]), "r"(b[1]));
}
__device__ __forceinline__ uint32_t pk(float lo, float hi) {
    uint32_t r;
    asm("cvt.rn.f16x2.f32 %0, %1, %2;" : "=r"(r) : "f"(hi), "f"(lo));
    return r;
}
#define MBAR_INIT(m, c) \
    asm volatile("mbarrier.init.shared.b64 [%0], %1;" :: "r"((uint32_t)(m)), "r"((uint32_t)(c)) : "memory")
#define MBAR_EXPECT_TX(m, b) \
    asm volatile("mbarrier.arrive.expect_tx.shared.b64 _, [%0], %1;" :: "r"((uint32_t)(m)), "r"((uint32_t)(b)) : "memory")
#define MBAR_WAIT(m, ph) do { \
    uint32_t _m = (uint32_t)(m), _p = (uint32_t)(ph), _d; \
    asm volatile("{\n\t.reg .pred p;\n\t" \
        "mbarrier.try_wait.parity.acquire.cta.shared::cta.b64 p, [%1], %2;\n\tselp.b32 %0,1,0,p;\n\t}" \
        : "=r"(_d) : "r"(_m), "r"(_p) : "memory"); \
    if (!_d) { asm volatile("{\n\t.reg .pred P1;\n\tWL_%=:\n\t" \
        "mbarrier.try_wait.parity.acquire.cta.shared::cta.b64 P1, [%0], %1, 0x989680;\n\t" \
        "@P1 bra.uni WD_%=;\n\tbra.uni WL_%=;\n\tWD_%=:\n\t}" :: "r"(_m), "r"(_p) : "memory"); } \
} while (0)
__device__ __forceinline__ void bulk_g2s(uint32_t dst, const void* src, uint32_t bytes, uint32_t mbar) {
    asm volatile("cp.async.bulk.shared::cluster.global.mbarrier::complete_tx::bytes [%0], [%1], %2, [%3];"
        :: "r"(dst), "l"(__cvta_generic_to_global(src)), "r"(bytes), "r"(mbar) : "memory");
}
#define NBAR_SYNC(id, cnt)   asm volatile("bar.sync %0, %1;"   :: "r"(id), "r"(cnt) : "memory")
#define NBAR_ARRIVE(id, cnt) asm volatile("bar.arrive %0, %1;" :: "r"(id), "r"(cnt) : "memory")

// ---------------------------------------------------------------------------
// Kernel 1: HMMA projection.
//   jt == 0: Q (j<32) / K (j>=32), 3-pass hi/lo (fp32-grade) — scheduled FIRST.
//   jt 1..4: V channels j0=(jt-1)*64, single-pass xh*wh (fp16-grade).
// ---------------------------------------------------------------------------
#define PJ_WH  0
#define PJ_WL  8192
#define PJ_X32 16384
#define PJ_XH  33792
#define PJ_XL  43008
#define PJ_SZ  52224

__global__ __launch_bounds__(256, 2) void proj_kernel(
    const float* __restrict__ x, const float* __restrict__ wv,
    const float* __restrict__ wq, const float* __restrict__ wk)
{
    extern __shared__ char smc[];
    float* xs32 = (float*)(smc + PJ_X32);
    const uint32_t sb = smem_u32(smc);
    const int tid = threadIdx.x, w = tid >> 5, lane = tid & 31;
    const int wn = w & 3, wj = w >> 2;
    const int b = blockIdx.z, n0 = blockIdx.x * 64, jt = blockIdx.y;
    const bool isQK = (jt == 0);

    float acc[4][4];
#pragma unroll
    for (int i = 0; i < 4; i++)
#pragma unroll
        for (int j = 0; j < 4; j++) acc[i][j] = 0.f;

    for (int c0 = 0; c0 < 256; c0 += 64) {
        __syncthreads();
        // ---- W chunk: 64j x 64c fp32 -> wh (+ wl if QK), sw128 rows
#pragma unroll
        for (int it = 0; it < 4; it++) {
            int f4 = tid + it * 256;
            int jl = f4 >> 4, c4 = f4 & 15;
            const float* src;
            if (!isQK) src = wv + (size_t)((jt - 1) * 64 + jl) * 256 + c0 + c4 * 4;
            else src = ((jl < 32) ? (wq + (size_t)jl * 256) : (wk + (size_t)(jl - 32) * 256)) + c0 + c4 * 4;
            float4 v = *(const float4*)src;
            __half h[4];
            h[0] = __float2half_rn(v.x); h[1] = __float2half_rn(v.y);
            h[2] = __float2half_rn(v.z); h[3] = __float2half_rn(v.w);
            *(uint2*)(smc + PJ_WH + jl * 128 + ((c4 * 8) ^ ((jl & 7) << 4))) = *(uint2*)h;
            if (isQK) {
                __half l[4];
                l[0] = __float2half_rn(v.x - __half2float(h[0]));
                l[1] = __float2half_rn(v.y - __half2float(h[1]));
                l[2] = __float2half_rn(v.z - __half2float(h[2]));
                l[3] = __float2half_rn(v.w - __half2float(h[3]));
                *(uint2*)(smc + PJ_WL + jl * 128 + ((c4 * 8) ^ ((jl & 7) << 4))) = *(uint2*)l;
            }
        }
        // ---- x chunk [64c][64n] fp32 coalesced -> xs32 (pitch 68)
#pragma unroll
        for (int it = 0; it < 4; it++) {
            int f4 = tid + it * 256;
            int cl = f4 >> 4, n4 = f4 & 15;
            float4 v = *(const float4*)(x + (size_t)(b * 256 + c0 + cl) * 4096 + n0 + n4 * 4);
            *(float4*)(xs32 + cl * 68 + n4 * 4) = v;
        }
        __syncthreads();
        // ---- register transpose + convert: xs32[c][n] -> xh (+ xl if QK)
        {
            int n = tid & 63, cq = tid >> 6;
#pragma unroll
            for (int i = 0; i < 4; i++) {
                int c = cq * 16 + i * 4;
                __half h[4], l[4];
#pragma unroll
                for (int k2 = 0; k2 < 4; k2++) {
                    float f = xs32[(c + k2) * 68 + n];
                    h[k2] = __float2half_rn(f);
                    if (isQK) l[k2] = __float2half_rn(f - __half2float(h[k2]));
                }
                *(uint2*)(smc + PJ_XH + n * 144 + c * 2) = *(uint2*)h;
                if (isQK) *(uint2*)(smc + PJ_XL + n * 144 + c * 2) = *(uint2*)l;
            }
        }
        __syncthreads();
        // ---- MMA: 4 k-steps of 16
#pragma unroll
        for (int kk = 0; kk < 4; kk++) {
            uint32_t ah[4], al[4];
            int arow = wn * 16 + (lane & 7) + ((lane & 8) ? 8 : 0);
            int aoff = arow * 144 + kk * 32 + ((lane & 16) ? 16 : 0);
            ldsm4(ah, sb + PJ_XH + aoff);
            if (isQK) ldsm4(al, sb + PJ_XL + aoff);
            int jr0 = wj * 32 + (lane & 7) + ((lane & 16) ? 8 : 0);
            int bcol = kk * 32 + ((lane & 8) ? 16 : 0);
#pragma unroll
            for (int nt2 = 0; nt2 < 2; nt2++) {
                int jrow = jr0 + nt2 * 16;
                uint32_t bh[4];
                ldsm4(bh, sb + PJ_WH + jrow * 128 + (bcol ^ ((jrow & 7) << 4)));
                mma16816(acc[nt2*2],   ah, bh);
                mma16816(acc[nt2*2+1], ah, bh + 2);
                if (isQK) {
                    mma16816(acc[nt2*2],   al, bh);
                    mma16816(acc[nt2*2+1], al, bh + 2);
                    uint32_t bl[4];
                    ldsm4(bl, sb + PJ_WL + jrow * 128 + (bcol ^ ((jrow & 7) << 4)));
                    mma16816(acc[nt2*2],   ah, bl);
                    mma16816(acc[nt2*2+1], ah, bl + 2);
                }
            }
        }
    }

    const int rA = wn * 16 + (lane >> 2), rB = rA + 8;
    if (isQK) {
#pragma unroll
        for (int t = 0; t < 4; t++) {
            int j = wj * 32 + (t >> 1) * 16 + (t & 1) * 8 + 2 * (lane & 3);
            bool isQ = j < 32;
            int qc = isQ ? j : j - 32;
            char* tb = (char*)((isQ ? g_qt : g_kt) + ((size_t)(b * 64 + blockIdx.x)) * 4096);
#pragma unroll
            for (int rr = 0; rr < 2; rr++) {
                int r = rr ? rB : rA;
                float v0 = acc[t][rr * 2], v1 = acc[t][rr * 2 + 1];
                __half h0 = __float2half_rn(v0), h1 = __float2half_rn(v1);
                __half l0 = __float2half_rn(v0 - __half2float(h0));
                __half l1 = __float2half_rn(v1 - __half2float(h1));
                uint32_t hp = (uint32_t)*(uint16_t*)&h0 | ((uint32_t)*(uint16_t*)&h1 << 16);
                uint32_t lp = (uint32_t)*(uint16_t*)&l0 | ((uint32_t)*(uint16_t*)&l1 << 16);
                *(uint32_t*)(tb + r * 128 + ((qc * 2)      ^ ((r & 7) << 4))) = hp;
                *(uint32_t*)(tb + r * 128 + ((64 + qc * 2) ^ ((r & 7) << 4))) = lp;
            }
        }
    } else {
        __syncthreads();
        __half* st = (__half*)(smc + PJ_XH);
#pragma unroll
        for (int t = 0; t < 4; t++) {
            int j = wj * 32 + (t >> 1) * 16 + (t & 1) * 8 + 2 * (lane & 3);
            st[j * 72 + rA]       = __float2half_rn(acc[t][0]);
            st[(j + 1) * 72 + rA] = __float2half_rn(acc[t][1]);
            st[j * 72 + rB]       = __float2half_rn(acc[t][2]);
            st[(j + 1) * 72 + rB] = __float2half_rn(acc[t][3]);
        }
        __syncthreads();
        char* tb = (char*)(g_vt + ((size_t)(b * 64 + blockIdx.x)) * 16384);
        int jl = tid >> 2, n8 = tid & 3;
        int c = (jt - 1) * 64 + jl;
#pragma unroll
        for (int hh = 0; hh < 2; hh++) {
            int nl = n8 * 16 + hh * 8;
            uint4 v = *(uint4*)(smc + PJ_XH + (jl * 72 + nl) * 2);
            *(uint4*)(tb + c * 128 + ((nl * 2) ^ ((c & 7) << 4))) = v;
        }
    }
}

// ---------------------------------------------------------------------------
// Kernel 2: warp-specialized HMMA flash attention (R11 protocol, 2 P slots).
// ---------------------------------------------------------------------------
#define OFF_P   0          /* 2 x 4608 (slot0 head doubles as 4KB Q staging) */
#define OFF_SC  9216       /* 2 x 32 f32 */
#define OFF_MX  9472       /* 2 x 2 x 32 f32 */
#define OFF_LS  9984       /* 2 x 32 f32 */
#define OFF_RDT 10240      /* 16384 */
#define OFF_K   26624      /* 2 x 8192 */
#define OFF_V   43008      /* 2 x 32768 */
#define OFF_BAR 108544
#define SMEM_SZ 108608

__global__ __launch_bounds__(256, 2) void attn_kernel(
    const float* __restrict__ x, const float* __restrict__ gamma,
    const float* __restrict__ beta, const float* __restrict__ mean,
    const float* __restrict__ var, float* __restrict__ out)
{
    extern __shared__ char smc[];
    float* rdt = (float*)(smc + OFF_RDT);
    float* ls  = (float*)(smc + OFF_LS);
    const uint32_t sb = smem_u32(smc);
    const uint32_t barK0 = sb + OFF_BAR, barK1 = sb + OFF_BAR + 8;
    const uint32_t barV0 = sb + OFF_BAR + 16, barV1 = sb + OFF_BAR + 24;
    const int tid = threadIdx.x, w = tid >> 5, lane = tid & 31;
    const int b = blockIdx.y, qt = blockIdx.x, qb = qt * 32;

    for (int i = tid; i < 4096; i += 256) {
        int dy = i >> 6, dx = i & 63;
        rdt[i] = 1.0f / (sqrtf((float)(dy * dy + dx * dx)) + 1.0f);
    }
    if (tid == 0) {
        MBAR_INIT(barK0, 1); MBAR_INIT(barK1, 1);
        MBAR_INIT(barV0, 1); MBAR_INIT(barV1, 1);
    }
    {   // Q staging into P slot0 head (4KB); consumed into regs before t=0 writes
        const char* qsrc = (const char*)(g_qt + ((size_t)(b * 64 + (qt >> 1))) * 4096)
                         + (size_t)(qt & 1) * 32 * 128;
        ((uint4*)smc)[tid] = ((const uint4*)qsrc)[tid];
    }
    __syncthreads();

    const __half* kt = g_kt + (size_t)b * 64 * 4096;
    const __half* vt = g_vt + (size_t)b * 64 * 16384;
    if (tid == 0) {   // prologue: K(0),K(1),V(0),V(1)
        MBAR_EXPECT_TX(barK0, 8192);  bulk_g2s(sb + OFF_K, kt, 8192, barK0);
        MBAR_EXPECT_TX(barK1, 8192);  bulk_g2s(sb + OFF_K + 8192, kt + 4096, 8192, barK1);
        MBAR_EXPECT_TX(barV0, 32768); bulk_g2s(sb + OFF_V, vt, 32768, barV0);
        MBAR_EXPECT_TX(barV1, 32768); bulk_g2s(sb + OFF_V + 32768, vt + 16384, 32768, barV1);
    }

    if (w < 4) {
        // ================= G1: GEMM1 + softmax =================
        const int wm = w & 1, wc = w >> 1;
        const int rxA = wm * 16 + (lane >> 2), rxB = rxA + 8;
        const int c0 = 2 * (lane & 3);
        const int rxAi = (qt & 1) * 32 + rxA, rxBi = rxAi + 8;
        const int ry = qt >> 1;

        uint32_t qf[2][2][4];
#pragma unroll
        for (int hl = 0; hl < 2; hl++)
#pragma unroll
            for (int kk = 0; kk < 2; kk++) {
                int row = wm * 16 + (lane & 7) + ((lane & 8) ? 8 : 0);
                int colb = hl * 64 + kk * 32 + ((lane & 16) ? 16 : 0);
                ldsm4(qf[hl][kk], sb + row * 128 + (colb ^ ((row & 7) << 4)));
            }
        NBAR_SYNC(1, 128);   // all G1 qf reads done before P slot0 writes at t=0

        float mA = -1e30f, mB = -1e30f, lA = 0.f, lB = 0.f;

        for (int t = 0; t < 64; t++) {
            MBAR_WAIT(((t & 1) ? barK1 : barK0), (t >> 1) & 1);
            const uint32_t bK = sb + OFF_K + (t & 1) * 8192;

            float s[4][4];
#pragma unroll
            for (int i = 0; i < 4; i++)
#pragma unroll
                for (int j = 0; j < 4; j++) s[i][j] = 0.f;
#pragma unroll
            for (int kk = 0; kk < 2; kk++) {
                int colb = kk * 32 + ((lane & 8) ? 16 : 0);
                int kr0 = wc * 32 + (lane & 7) + ((lane & 16) ? 8 : 0);
                uint32_t bh0[4], bh1[4], bl0[4], bl1[4];
                ldsm4(bh0, bK + kr0 * 128 + (colb ^ ((kr0 & 7) << 4)));
                ldsm4(bl0, bK + kr0 * 128 + ((colb + 64) ^ ((kr0 & 7) << 4)));
                int kr1 = kr0 + 16;
                ldsm4(bh1, bK + kr1 * 128 + (colb ^ ((kr1 & 7) << 4)));
                ldsm4(bl1, bK + kr1 * 128 + ((colb + 64) ^ ((kr1 & 7) << 4)));
                mma16816(s[0], qf[0][kk], bh0);
                mma16816(s[1], qf[0][kk], bh0 + 2);
                mma16816(s[2], qf[0][kk], bh1);
                mma16816(s[3], qf[0][kk], bh1 + 2);
                mma16816(s[0], qf[1][kk], bh0);
                mma16816(s[1], qf[1][kk], bh0 + 2);
                mma16816(s[2], qf[1][kk], bh1);
                mma16816(s[3], qf[1][kk], bh1 + 2);
                mma16816(s[0], qf[0][kk], bl0);
                mma16816(s[1], qf[0][kk], bl0 + 2);
                mma16816(s[2], qf[0][kk], bl1);
                mma16816(s[3], qf[0][kk], bl1 + 2);
            }

            const float* rdtp = rdt + ((ry > t) ? (ry - t) : (t - ry)) * 64;
            float tmA = -1e30f, tmB = -1e30f;
#pragma unroll
            for (int idx = 0; idx < 4; idx++) {
                int c = wc * 32 + (idx >> 1) * 16 + (idx & 1) * 8 + c0;
                int d0 = rxAi - c;     d0 = d0 < 0 ? -d0 : d0;
                int d1 = rxAi - c - 1; d1 = d1 < 0 ? -d1 : d1;
                int d2 = rxBi - c;     d2 = d2 < 0 ? -d2 : d2;
                int d3 = rxBi - c - 1; d3 = d3 < 0 ? -d3 : d3;
                s[idx][0] *= rdtp[d0];
                s[idx][1] *= rdtp[d1];
                s[idx][2] *= rdtp[d2];
                s[idx][3] *= rdtp[d3];
                tmA = fmaxf(tmA, fmaxf(s[idx][0], s[idx][1]));
                tmB = fmaxf(tmB, fmaxf(s[idx][2], s[idx][3]));
            }
            tmA = fmaxf(tmA, __shfl_xor_sync(0xffffffffu, tmA, 1));
            tmA = fmaxf(tmA, __shfl_xor_sync(0xffffffffu, tmA, 2));
            tmB = fmaxf(tmB, __shfl_xor_sync(0xffffffffu, tmB, 1));
            tmB = fmaxf(tmB, __shfl_xor_sync(0xffffffffu, tmB, 2));
            float* mxs = (float*)(smc + OFF_MX + (t & 1) * 256);
            if ((lane & 3) == 0) {
                mxs[wc * 32 + rxA] = tmA;
                mxs[wc * 32 + rxB] = tmB;
            }
            NBAR_SYNC(1, 128);
            if (tid == 0 && t + 2 < 64) {
                uint32_t bk = (t & 1) ? barK1 : barK0;
                MBAR_EXPECT_TX(bk, 8192);
                bulk_g2s(sb + OFF_K + (t & 1) * 8192, kt + (size_t)(t + 2) * 4096, 8192, bk);
            }
            float gmA = fmaxf(mxs[rxA], mxs[32 + rxA]);
            float gmB = fmaxf(mxs[rxB], mxs[32 + rxB]);
            float mnA = fmaxf(mA, gmA), mnB = fmaxf(mB, gmB);
            float scA = __expf(mA - mnA), scB = __expf(mB - mnB);
            mA = mnA; mB = mnB;

            float sumA = 0.f, sumB = 0.f;
            uint32_t pp[4][2];
#pragma unroll
            for (int idx = 0; idx < 4; idx++) {
                float p0 = __expf(s[idx][0] - mnA), p1 = __expf(s[idx][1] - mnA);
                float p2 = __expf(s[idx][2] - mnB), p3 = __expf(s[idx][3] - mnB);
                sumA += p0 + p1; sumB += p2 + p3;
                pp[idx][0] = pk(p0, p1);
                pp[idx][1] = pk(p2, p3);
            }
            sumA += __shfl_xor_sync(0xffffffffu, sumA, 1);
            sumA += __shfl_xor_sync(0xffffffffu, sumA, 2);
            sumB += __shfl_xor_sync(0xffffffffu, sumB, 1);
            sumB += __shfl_xor_sync(0xffffffffu, sumB, 2);
            lA = lA * scA + sumA;
            lB = lB * scB + sumB;

            if (t >= 2) NBAR_SYNC(8 + (t & 1), 256);   // slot free (G2 done t-2)
            char* Pb = smc + OFF_P + (t & 1) * 4608;
#pragma unroll
            for (int idx = 0; idx < 4; idx++) {
                int c = wc * 32 + (idx >> 1) * 16 + (idx & 1) * 8 + c0;
                *(uint32_t*)(Pb + (rxA * 72 + c) * 2) = pp[idx][0];
                *(uint32_t*)(Pb + (rxB * 72 + c) * 2) = pp[idx][1];
            }
            if (wc == 0 && (lane & 3) == 0) {
                float* scb = (float*)(smc + OFF_SC + (t & 1) * 128);
                scb[rxA] = scA;
                scb[rxB] = scB;
            }
            NBAR_ARRIVE(2 + (t & 1), 256);             // P(t) ready
        }
        if ((lane & 3) == 0) {
            ls[wc * 32 + rxA] = lA;
            ls[wc * 32 + rxB] = lB;
        }
        NBAR_SYNC(6, 256);   // ls visible to G2
        NBAR_SYNC(7, 256);   // G2's Ys writes done
    } else {
        // ================= G2: rescale + GEMM2 =================
        const int wq2 = w - 4;
        const int c0 = 2 * (lane & 3);
        const int r0 = lane >> 2;

        float y[2][8][4];
#pragma unroll
        for (int bd = 0; bd < 2; bd++)
#pragma unroll
            for (int i = 0; i < 8; i++)
#pragma unroll
                for (int j = 0; j < 4; j++) y[bd][i][j] = 0.f;

        for (int t = 0; t < 64; t++) {
            NBAR_SYNC(2 + (t & 1), 256);      // P(t), sc(t) ready
            const float* scb = (const float*)(smc + OFF_SC + (t & 1) * 128);
            float s0 = scb[r0], s1 = scb[r0 + 8], s2 = scb[r0 + 16], s3 = scb[r0 + 24];
            bool nor = (s0 == 1.f) & (s1 == 1.f) & (s2 == 1.f) & (s3 == 1.f);
            if (!__all_sync(0xffffffffu, nor)) {
#pragma unroll
                for (int i = 0; i < 8; i++) {
                    y[0][i][0] *= s0; y[0][i][1] *= s0;
                    y[0][i][2] *= s1; y[0][i][3] *= s1;
                    y[1][i][0] *= s2; y[1][i][1] *= s2;
                    y[1][i][2] *= s3; y[1][i][3] *= s3;
                }
            }
            MBAR_WAIT(((t & 1) ? barV1 : barV0), (t >> 1) & 1);
            const uint32_t bV = sb + OFF_V + (t & 1) * 32768;
            const uint32_t Pb = sb + OFF_P + (t & 1) * 4608;
#pragma unroll
            for (int kk = 0; kk < 4; kk++) {
                uint32_t pa0[4], pa1[4];
                int pr = (lane & 7) + ((lane & 8) ? 8 : 0);
                int pc = kk * 16 + ((lane & 16) ? 8 : 0);
                ldsm4(pa0, Pb + (pr * 72 + pc) * 2);
                ldsm4(pa1, Pb + ((pr + 16) * 72 + pc) * 2);
                int colb = kk * 32 + ((lane & 8) ? 16 : 0);
#pragma unroll
                for (int np = 0; np < 4; np++) {
                    int vrow = wq2 * 64 + np * 16 + (lane & 7) + ((lane & 16) ? 8 : 0);
                    uint32_t bv[4];
                    ldsm4(bv, bV + vrow * 128 + (colb ^ ((vrow & 7) << 4)));
                    mma16816(y[0][np*2],   pa0, bv);
                    mma16816(y[0][np*2+1], pa0, bv + 2);
                    mma16816(y[1][np*2],   pa1, bv);
                    mma16816(y[1][np*2+1], pa1, bv + 2);
                }
            }
            NBAR_SYNC(14, 128);               // all G2 done with V(t)/P(t)
            if (tid == 128 && t + 2 < 64) {
                uint32_t bv2 = (t & 1) ? barV1 : barV0;
                MBAR_EXPECT_TX(bv2, 32768);
                bulk_g2s(sb + OFF_V + (t & 1) * 32768, vt + (size_t)(t + 2) * 16384, 32768, bv2);
            }
            if (t < 62) NBAR_ARRIVE(8 + (t & 1), 256);   // P slot free
        }

        NBAR_SYNC(6, 256);   // ls visible
        float rl[4];
#pragma unroll
        for (int q = 0; q < 4; q++) {
            int r = r0 + q * 8;
            rl[q] = 1.f / (ls[r] + ls[32 + r]);
        }
        NBAR_SYNC(14, 128);  // all G2 read ls before Ys overwrite
        float* Ys = (float*)smc;   // [32][260] f32 (overlaps P/sc/mx/ls/rdt — all dead)
#pragma unroll
        for (int bd = 0; bd < 2; bd++)
#pragma unroll
            for (int nt = 0; nt < 8; nt++) {
                int c = wq2 * 64 + (nt >> 1) * 16 + (nt & 1) * 8 + c0;
                int rA = bd * 16 + r0, rB = rA + 8;
                Ys[rA * 260 + c]     = y[bd][nt][0] * rl[bd * 2];
                Ys[rA * 260 + c + 1] = y[bd][nt][1] * rl[bd * 2];
                Ys[rB * 260 + c]     = y[bd][nt][2] * rl[bd * 2 + 1];
                Ys[rB * 260 + c + 1] = y[bd][nt][3] * rl[bd * 2 + 1];
            }
        NBAR_SYNC(7, 256);   // Ys published
    }

    // ---- common epilogue: BN + ReLU + residual (Ys visible after bar 7)
    float* Ys = (float*)smc;
    const int n = tid & 31, cg = tid >> 5;
#pragma unroll 4
    for (int it = 0; it < 32; it++) {
        int c = it * 8 + cg;
        float inv = gamma[c] * rsqrtf(var[c] + 1e-5f);
        float add = fmaf(-mean[c], inv, beta[c]);
        size_t idx = ((size_t)b * C_ + c) * N_ + qb + n;
        float yv = Ys[n * 260 + c];
        out[idx] = fmaxf(fmaf(yv, inv, add), 0.f) + x[idx];
    }
}

// ---------------------------------------------------------------------------
extern "C" void kernel_launch(void* const* d_in, const int* in_sizes, int n_in,
                              void* d_out, int out_size)
{
    (void)in_sizes; (void)n_in; (void)out_size;
    const float* x     = (const float*)d_in[0];
    const float* wv    = (const float*)d_in[1];
    const float* wq    = (const float*)d_in[2];
    const float* wk    = (const float*)d_in[3];
    const float* gamma = (const float*)d_in[4];
    const float* beta  = (const float*)d_in[5];
    const float* mean  = (const float*)d_in[6];
    const float* var   = (const float*)d_in[7];
    float* out = (float*)d_out;

    cudaFuncSetAttribute(proj_kernel, cudaFuncAttributeMaxDynamicSharedMemorySize, PJ_SZ);
    proj_kernel<<<dim3(64, 5, B_), 256, PJ_SZ>>>(x, wv, wq, wk);
    cudaFuncSetAttribute(attn_kernel, cudaFuncAttributeMaxDynamicSharedMemorySize, SMEM_SZ);
    attn_kernel<<<dim3(128, B_), 256, SMEM_SZ>>>(x, gamma, beta, mean, var, out);
}

// round 14
// speedup vs baseline: 1.0944x; 1.0771x over previous
#include <cuda_runtime.h>
#include <cuda_fp16.h>
#include <stdint.h>

#define B_ 4
#define C_ 256
#define N_ 4096

// ---------------- device scratch (swizzled tile layouts, attn-ready) --------
__device__ __align__(256) __half g_qt [(size_t)B_ * 64 * 4096]; // 8KB q-tiles [r][qh32|ql32] sw128
__device__ __align__(256) __half g_kt [(size_t)B_ * 64 * 4096]; // 8KB k-tiles
__device__ __align__(256) __half g_vt [(size_t)B_ * 64 * 16384];// 32KB V^T tiles [c][n] sw128

// ---------------- asm helpers ----------------
__device__ __forceinline__ uint32_t smem_u32(const void* p) {
    uint32_t a;
    asm("{ .reg .u64 t; cvta.to.shared.u64 t, %1; cvt.u32.u64 %0, t; }" : "=r"(a) : "l"(p));
    return a;
}
__device__ __forceinline__ void ldsm4(uint32_t* r, uint32_t a) {
    asm volatile("ldmatrix.sync.aligned.m8n8.x4.shared.b16 {%0,%1,%2,%3}, [%4];"
        : "=r"(r[0]), "=r"(r[1]), "=r"(r[2]), "=r"(r[3]) : "r"(a));
}
__device__ __forceinline__ void mma16816(float* c, const uint32_t* a, const uint32_t* b) {
    asm volatile("mma.sync.aligned.m16n8k16.row.col.f32.f16.f16.f32 "
        "{%0,%1,%2,%3}, {%4,%5,%6,%7}, {%8,%9}, {%0,%1,%2,%3};"
        : "+f"(c[0]), "+f"(c[1]), "+f"(c[2]), "+f"(c[3])
        : "r"(a[0]), "r"(a[1]), "r"(a[2]), "r"(a[3]), "r"(b[0]), "r"(b[1]));
}
__device__ __forceinline__ uint32_t pk(float lo, float hi) {
    uint32_t r;
    asm("cvt.rn.f16x2.f32 %0, %1, %2;" : "=r"(r) : "f"(hi), "f"(lo));
    return r;
}
#define MBAR_INIT(m, c) \
    asm volatile("mbarrier.init.shared.b64 [%0], %1;" :: "r"((uint32_t)(m)), "r"((uint32_t)(c)) : "memory")
#define MBAR_EXPECT_TX(m, b) \
    asm volatile("mbarrier.arrive.expect_tx.shared.b64 _, [%0], %1;" :: "r"((uint32_t)(m)), "r"((uint32_t)(b)) : "memory")
#define MBAR_WAIT(m, ph) do { \
    uint32_t _m = (uint32_t)(m), _p = (uint32_t)(ph), _d; \
    asm volatile("{\n\t.reg .pred p;\n\t" \
        "mbarrier.try_wait.parity.acquire.cta.shared::cta.b64 p, [%1], %2;\n\tselp.b32 %0,1,0,p;\n\t}" \
        : "=r"(_d) : "r"(_m), "r"(_p) : "memory"); \
    if (!_d) { asm volatile("{\n\t.reg .pred P1;\n\tWL_%=:\n\t" \
        "mbarrier.try_wait.parity.acquire.cta.shared::cta.b64 P1, [%0], %1, 0x989680;\n\t" \
        "@P1 bra.uni WD_%=;\n\tbra.uni WL_%=;\n\tWD_%=:\n\t}" :: "r"(_m), "r"(_p) : "memory"); } \
} while (0)
__device__ __forceinline__ void bulk_g2s(uint32_t dst, const void* src, uint32_t bytes, uint32_t mbar) {
    asm volatile("cp.async.bulk.shared::cluster.global.mbarrier::complete_tx::bytes [%0], [%1], %2, [%3];"
        :: "r"(dst), "l"(__cvta_generic_to_global(src)), "r"(bytes), "r"(mbar) : "memory");
}
#define NBAR_SYNC(id, cnt)   asm volatile("bar.sync %0, %1;"   :: "r"(id), "r"(cnt) : "memory")
#define NBAR_ARRIVE(id, cnt) asm volatile("bar.arrive %0, %1;" :: "r"(id), "r"(cnt) : "memory")

// ---------------------------------------------------------------------------
// Kernel 1: UNIFIED HMMA projection — one CTA per 64-n-tile computes ALL
// 320 output channels (V 256 j single-pass + QK 64 j 3-pass hi/lo).
// Grid 64 x B = 256 CTAs -> single wave at occ 2. x loaded once per tile.
// Warp (wn = w&3: 16 n-rows, wj = w>>2: j half).
// ---------------------------------------------------------------------------
#define PJ_WV   0        /* V weights chunk: 256j x 64c fp16 sw128 = 32768 */
#define PJ_WQH  32768    /* QK hi: 64j x 64c = 8192 */
#define PJ_WQL  40960    /* QK lo: 8192 */
#define PJ_X32  49152    /* x chunk [64c][68] f32 = 17408 */
#define PJ_XH   66560    /* xh [64n][72c] pitch 144B = 9216 */
#define PJ_XL   75776    /* xl = 9216 */
#define PJ_SZ   84992
/* V staging (epilogue, overlaps PJ_WV..): [256j][72n] halves = 36864 */

__global__ __launch_bounds__(256, 2) void proj_kernel(
    const float* __restrict__ x, const float* __restrict__ wv,
    const float* __restrict__ wq, const float* __restrict__ wk)
{
    extern __shared__ char smc[];
    float* xs32 = (float*)(smc + PJ_X32);
    const uint32_t sb = smem_u32(smc);
    const int tid = threadIdx.x, w = tid >> 5, lane = tid & 31;
    const int wn = w & 3, wj = w >> 2;
    const int b = blockIdx.y, n0 = blockIdx.x * 64;

    float accV[16][4];
    float accQ[4][4];
#pragma unroll
    for (int i = 0; i < 16; i++)
#pragma unroll
        for (int j = 0; j < 4; j++) accV[i][j] = 0.f;
#pragma unroll
    for (int i = 0; i < 4; i++)
#pragma unroll
        for (int j = 0; j < 4; j++) accQ[i][j] = 0.f;

    for (int c0 = 0; c0 < 256; c0 += 64) {
        __syncthreads();   // prior chunk MMA reads done
        // ---- W_V chunk: 256j x 64c -> fp16 sw128
#pragma unroll
        for (int it = 0; it < 16; it++) {
            int f4 = tid + it * 256;
            int jl = f4 >> 4, c4 = f4 & 15;
            float4 v = *(const float4*)(wv + (size_t)jl * 256 + c0 + c4 * 4);
            __half h[4];
            h[0] = __float2half_rn(v.x); h[1] = __float2half_rn(v.y);
            h[2] = __float2half_rn(v.z); h[3] = __float2half_rn(v.w);
            *(uint2*)(smc + PJ_WV + jl * 128 + ((c4 * 8) ^ ((jl & 7) << 4))) = *(uint2*)h;
        }
        // ---- W_QK chunk: 64j (Q 0..31, K 32..63) hi/lo
#pragma unroll
        for (int it = 0; it < 4; it++) {
            int f4 = tid + it * 256;
            int jl = f4 >> 4, c4 = f4 & 15;
            const float* src = ((jl < 32) ? (wq + (size_t)jl * 256)
                                          : (wk + (size_t)(jl - 32) * 256)) + c0 + c4 * 4;
            float4 v = *(const float4*)src;
            __half h[4], l[4];
            h[0] = __float2half_rn(v.x); h[1] = __float2half_rn(v.y);
            h[2] = __float2half_rn(v.z); h[3] = __float2half_rn(v.w);
            l[0] = __float2half_rn(v.x - __half2float(h[0]));
            l[1] = __float2half_rn(v.y - __half2float(h[1]));
            l[2] = __float2half_rn(v.z - __half2float(h[2]));
            l[3] = __float2half_rn(v.w - __half2float(h[3]));
            *(uint2*)(smc + PJ_WQH + jl * 128 + ((c4 * 8) ^ ((jl & 7) << 4))) = *(uint2*)h;
            *(uint2*)(smc + PJ_WQL + jl * 128 + ((c4 * 8) ^ ((jl & 7) << 4))) = *(uint2*)l;
        }
        // ---- x chunk [64c][64n] coalesced
#pragma unroll
        for (int it = 0; it < 4; it++) {
            int f4 = tid + it * 256;
            int cl = f4 >> 4, n4 = f4 & 15;
            float4 v = *(const float4*)(x + (size_t)(b * 256 + c0 + cl) * 4096 + n0 + n4 * 4);
            *(float4*)(xs32 + cl * 68 + n4 * 4) = v;
        }
        __syncthreads();
        // ---- register transpose + hi/lo convert
        {
            int n = tid & 63, cq = tid >> 6;
#pragma unroll
            for (int i = 0; i < 4; i++) {
                int c = cq * 16 + i * 4;
                __half h[4], l[4];
#pragma unroll
                for (int k2 = 0; k2 < 4; k2++) {
                    float f = xs32[(c + k2) * 68 + n];
                    h[k2] = __float2half_rn(f);
                    l[k2] = __float2half_rn(f - __half2float(h[k2]));
                }
                *(uint2*)(smc + PJ_XH + n * 144 + c * 2) = *(uint2*)h;
                *(uint2*)(smc + PJ_XL + n * 144 + c * 2) = *(uint2*)l;
            }
        }
        __syncthreads();
        // ---- MMA: 4 k-steps of 16
#pragma unroll
        for (int kk = 0; kk < 4; kk++) {
            uint32_t ah[4], al[4];
            int arow = wn * 16 + (lane & 7) + ((lane & 8) ? 8 : 0);
            int aoff = arow * 144 + kk * 32 + ((lane & 16) ? 16 : 0);
            ldsm4(ah, sb + PJ_XH + aoff);
            ldsm4(al, sb + PJ_XL + aoff);
            int bcol = kk * 32 + ((lane & 8) ? 16 : 0);
            int jrb = (lane & 7) + ((lane & 16) ? 8 : 0);
            // V: 8 j-groups of 16 (this warp's 128-j half), single-pass
#pragma unroll
            for (int jp = 0; jp < 8; jp++) {
                int jrow = wj * 128 + jp * 16 + jrb;
                uint32_t bh[4];
                ldsm4(bh, sb + PJ_WV + jrow * 128 + (bcol ^ ((jrow & 7) << 4)));
                mma16816(accV[jp*2],   ah, bh);
                mma16816(accV[jp*2+1], ah, bh + 2);
            }
            // QK: 2 j-groups of 16 (this warp's 32-j half), 3-pass
#pragma unroll
            for (int jq = 0; jq < 2; jq++) {
                int jrow = wj * 32 + jq * 16 + jrb;
                uint32_t bh[4], bl[4];
                ldsm4(bh, sb + PJ_WQH + jrow * 128 + (bcol ^ ((jrow & 7) << 4)));
                ldsm4(bl, sb + PJ_WQL + jrow * 128 + (bcol ^ ((jrow & 7) << 4)));
                mma16816(accQ[jq*2],   ah, bh);
                mma16816(accQ[jq*2+1], ah, bh + 2);
                mma16816(accQ[jq*2],   al, bh);
                mma16816(accQ[jq*2+1], al, bh + 2);
                mma16816(accQ[jq*2],   ah, bl);
                mma16816(accQ[jq*2+1], ah, bl + 2);
            }
        }
    }

    const int rA = wn * 16 + (lane >> 2), rB = rA + 8;
    const int c0l = 2 * (lane & 3);

    // ---- QK epilogue: hi/lo split, direct to swizzled g_qt/g_kt (regs only)
#pragma unroll
    for (int t = 0; t < 4; t++) {
        int j = wj * 32 + (t >> 1) * 16 + (t & 1) * 8 + c0l;
        bool isQ = j < 32;
        int qc = isQ ? j : j - 32;
        char* tb = (char*)((isQ ? g_qt : g_kt) + ((size_t)(b * 64 + blockIdx.x)) * 4096);
#pragma unroll
        for (int rr = 0; rr < 2; rr++) {
            int r = rr ? rB : rA;
            float v0 = accQ[t][rr * 2], v1 = accQ[t][rr * 2 + 1];
            __half h0 = __float2half_rn(v0), h1 = __float2half_rn(v1);
            __half l0 = __float2half_rn(v0 - __half2float(h0));
            __half l1 = __float2half_rn(v1 - __half2float(h1));
            uint32_t hp = (uint32_t)*(uint16_t*)&h0 | ((uint32_t)*(uint16_t*)&h1 << 16);
            uint32_t lp = (uint32_t)*(uint16_t*)&l0 | ((uint32_t)*(uint16_t*)&l1 << 16);
            *(uint32_t*)(tb + r * 128 + ((qc * 2)      ^ ((r & 7) << 4))) = hp;
            *(uint32_t*)(tb + r * 128 + ((64 + qc * 2) ^ ((r & 7) << 4))) = lp;
        }
    }

    // ---- V epilogue: stage [256j][72n] in smem (overlaps W regions), scatter
    __syncthreads();   // all MMA smem reads done
    __half* st = (__half*)smc;
#pragma unroll
    for (int jp = 0; jp < 8; jp++)
#pragma unroll
        for (int h = 0; h < 2; h++) {
            int j = wj * 128 + jp * 16 + h * 8 + c0l;
            st[j * 72 + rA]       = __float2half_rn(accV[jp*2+h][0]);
            st[(j + 1) * 72 + rA] = __float2half_rn(accV[jp*2+h][1]);
            st[j * 72 + rB]       = __float2half_rn(accV[jp*2+h][2]);
            st[(j + 1) * 72 + rB] = __float2half_rn(accV[jp*2+h][3]);
        }
    __syncthreads();
    {
        char* tb = (char*)(g_vt + ((size_t)(b * 64 + blockIdx.x)) * 16384);
        int c = tid;   // 0..255
#pragma unroll
        for (int hh = 0; hh < 8; hh++) {
            int nl = hh * 8;
            uint4 v = *(uint4*)(st + c * 72 + nl);
            *(uint4*)(tb + c * 128 + ((nl * 2) ^ ((c & 7) << 4))) = v;
        }
    }
}

// ---------------------------------------------------------------------------
// Kernel 2: warp-specialized HMMA flash attention (R11 protocol, unchanged).
// ---------------------------------------------------------------------------
#define OFF_P   0          /* 2 x 4608 (slot0 head doubles as 4KB Q staging) */
#define OFF_SC  9216       /* 2 x 32 f32 */
#define OFF_MX  9472       /* 2 x 2 x 32 f32 */
#define OFF_LS  9984       /* 2 x 32 f32 */
#define OFF_RDT 10240      /* 16384 */
#define OFF_K   26624      /* 2 x 8192 */
#define OFF_V   43008      /* 2 x 32768 */
#define OFF_BAR 108544
#define SMEM_SZ 108608

__global__ __launch_bounds__(256, 2) void attn_kernel(
    const float* __restrict__ x, const float* __restrict__ gamma,
    const float* __restrict__ beta, const float* __restrict__ mean,
    const float* __restrict__ var, float* __restrict__ out)
{
    extern __shared__ char smc[];
    float* rdt = (float*)(smc + OFF_RDT);
    float* ls  = (float*)(smc + OFF_LS);
    const uint32_t sb = smem_u32(smc);
    const uint32_t barK0 = sb + OFF_BAR, barK1 = sb + OFF_BAR + 8;
    const uint32_t barV0 = sb + OFF_BAR + 16, barV1 = sb + OFF_BAR + 24;
    const int tid = threadIdx.x, w = tid >> 5, lane = tid & 31;
    const int b = blockIdx.y, qt = blockIdx.x, qb = qt * 32;

    for (int i = tid; i < 4096; i += 256) {
        int dy = i >> 6, dx = i & 63;
        rdt[i] = 1.0f / (sqrtf((float)(dy * dy + dx * dx)) + 1.0f);
    }
    if (tid == 0) {
        MBAR_INIT(barK0, 1); MBAR_INIT(barK1, 1);
        MBAR_INIT(barV0, 1); MBAR_INIT(barV1, 1);
    }
    {   // Q staging into P slot0 head (4KB); consumed into regs before t=0 writes
        const char* qsrc = (const char*)(g_qt + ((size_t)(b * 64 + (qt >> 1))) * 4096)
                         + (size_t)(qt & 1) * 32 * 128;
        ((uint4*)smc)[tid] = ((const uint4*)qsrc)[tid];
    }
    __syncthreads();

    const __half* kt = g_kt + (size_t)b * 64 * 4096;
    const __half* vt = g_vt + (size_t)b * 64 * 16384;
    if (tid == 0) {   // prologue: K(0),K(1),V(0),V(1)
        MBAR_EXPECT_TX(barK0, 8192);  bulk_g2s(sb + OFF_K, kt, 8192, barK0);
        MBAR_EXPECT_TX(barK1, 8192);  bulk_g2s(sb + OFF_K + 8192, kt + 4096, 8192, barK1);
        MBAR_EXPECT_TX(barV0, 32768); bulk_g2s(sb + OFF_V, vt, 32768, barV0);
        MBAR_EXPECT_TX(barV1, 32768); bulk_g2s(sb + OFF_V + 32768, vt + 16384, 32768, barV1);
    }

    if (w < 4) {
        // ================= G1: GEMM1 + softmax =================
        const int wm = w & 1, wc = w >> 1;
        const int rxA = wm * 16 + (lane >> 2), rxB = rxA + 8;
        const int c0 = 2 * (lane & 3);
        const int rxAi = (qt & 1) * 32 + rxA, rxBi = rxAi + 8;
        const int ry = qt >> 1;

        uint32_t qf[2][2][4];
#pragma unroll
        for (int hl = 0; hl < 2; hl++)
#pragma unroll
            for (int kk = 0; kk < 2; kk++) {
                int row = wm * 16 + (lane & 7) + ((lane & 8) ? 8 : 0);
                int colb = hl * 64 + kk * 32 + ((lane & 16) ? 16 : 0);
                ldsm4(qf[hl][kk], sb + row * 128 + (colb ^ ((row & 7) << 4)));
            }
        NBAR_SYNC(1, 128);   // all G1 qf reads done before P slot0 writes at t=0

        float mA = -1e30f, mB = -1e30f, lA = 0.f, lB = 0.f;

        for (int t = 0; t < 64; t++) {
            MBAR_WAIT(((t & 1) ? barK1 : barK0), (t >> 1) & 1);
            const uint32_t bK = sb + OFF_K + (t & 1) * 8192;

            float s[4][4];
#pragma unroll
            for (int i = 0; i < 4; i++)
#pragma unroll
                for (int j = 0; j < 4; j++) s[i][j] = 0.f;
#pragma unroll
            for (int kk = 0; kk < 2; kk++) {
                int colb = kk * 32 + ((lane & 8) ? 16 : 0);
                int kr0 = wc * 32 + (lane & 7) + ((lane & 16) ? 8 : 0);
                uint32_t bh0[4], bh1[4], bl0[4], bl1[4];
                ldsm4(bh0, bK + kr0 * 128 + (colb ^ ((kr0 & 7) << 4)));
                ldsm4(bl0, bK + kr0 * 128 + ((colb + 64) ^ ((kr0 & 7) << 4)));
                int kr1 = kr0 + 16;
                ldsm4(bh1, bK + kr1 * 128 + (colb ^ ((kr1 & 7) << 4)));
                ldsm4(bl1, bK + kr1 * 128 + ((colb + 64) ^ ((kr1 & 7) << 4)));
                mma16816(s[0], qf[0][kk], bh0);
                mma16816(s[1], qf[0][kk], bh0 + 2);
                mma16816(s[2], qf[0][kk], bh1);
                mma16816(s[3], qf[0][kk], bh1 + 2);
                mma16816(s[0], qf[1][kk], bh0);
                mma16816(s[1], qf[1][kk], bh0 + 2);
                mma16816(s[2], qf[1][kk], bh1);
                mma16816(s[3], qf[1][kk], bh1 + 2);
                mma16816(s[0], qf[0][kk], bl0);
                mma16816(s[1], qf[0][kk], bl0 + 2);
                mma16816(s[2], qf[0][kk], bl1);
                mma16816(s[3], qf[0][kk], bl1 + 2);
            }

            const float* rdtp = rdt + ((ry > t) ? (ry - t) : (t - ry)) * 64;
            float tmA = -1e30f, tmB = -1e30f;
#pragma unroll
            for (int idx = 0; idx < 4; idx++) {
                int c = wc * 32 + (idx >> 1) * 16 + (idx & 1) * 8 + c0;
                int d0 = rxAi - c;     d0 = d0 < 0 ? -d0 : d0;
                int d1 = rxAi - c - 1; d1 = d1 < 0 ? -d1 : d1;
                int d2 = rxBi - c;     d2 = d2 < 0 ? -d2 : d2;
                int d3 = rxBi - c - 1; d3 = d3 < 0 ? -d3 : d3;
                s[idx][0] *= rdtp[d0];
                s[idx][1] *= rdtp[d1];
                s[idx][2] *= rdtp[d2];
                s[idx][3] *= rdtp[d3];
                tmA = fmaxf(tmA, fmaxf(s[idx][0], s[idx][1]));
                tmB = fmaxf(tmB, fmaxf(s[idx][2], s[idx][3]));
            }
            tmA = fmaxf(tmA, __shfl_xor_sync(0xffffffffu, tmA, 1));
            tmA = fmaxf(tmA, __shfl_xor_sync(0xffffffffu, tmA, 2));
            tmB = fmaxf(tmB, __shfl_xor_sync(0xffffffffu, tmB, 1));
            tmB = fmaxf(tmB, __shfl_xor_sync(0xffffffffu, tmB, 2));
            float* mxs = (float*)(smc + OFF_MX + (t & 1) * 256);
            if ((lane & 3) == 0) {
                mxs[wc * 32 + rxA] = tmA;
                mxs[wc * 32 + rxB] = tmB;
            }
            NBAR_SYNC(1, 128);
            if (tid == 0 && t + 2 < 64) {
                uint32_t bk = (t & 1) ? barK1 : barK0;
                MBAR_EXPECT_TX(bk, 8192);
                bulk_g2s(sb + OFF_K + (t & 1) * 8192, kt + (size_t)(t + 2) * 4096, 8192, bk);
            }
            float gmA = fmaxf(mxs[rxA], mxs[32 + rxA]);
            float gmB = fmaxf(mxs[rxB], mxs[32 + rxB]);
            float mnA = fmaxf(mA, gmA), mnB = fmaxf(mB, gmB);
            float scA = __expf(mA - mnA), scB = __expf(mB - mnB);
            mA = mnA; mB = mnB;

            float sumA = 0.f, sumB = 0.f;
            uint32_t pp[4][2];
#pragma unroll
            for (int idx = 0; idx < 4; idx++) {
                float p0 = __expf(s[idx][0] - mnA), p1 = __expf(s[idx][1] - mnA);
                float p2 = __expf(s[idx][2] - mnB), p3 = __expf(s[idx][3] - mnB);
                sumA += p0 + p1; sumB += p2 + p3;
                pp[idx][0] = pk(p0, p1);
                pp[idx][1] = pk(p2, p3);
            }
            sumA += __shfl_xor_sync(0xffffffffu, sumA, 1);
            sumA += __shfl_xor_sync(0xffffffffu, sumA, 2);
            sumB += __shfl_xor_sync(0xffffffffu, sumB, 1);
            sumB += __shfl_xor_sync(0xffffffffu, sumB, 2);
            lA = lA * scA + sumA;
            lB = lB * scB + sumB;

            if (t >= 2) NBAR_SYNC(8 + (t & 1), 256);   // slot free (G2 done t-2)
            char* Pb = smc + OFF_P + (t & 1) * 4608;
#pragma unroll
            for (int idx = 0; idx < 4; idx++) {
                int c = wc * 32 + (idx >> 1) * 16 + (idx & 1) * 8 + c0;
                *(uint32_t*)(Pb + (rxA * 72 + c) * 2) = pp[idx][0];
                *(uint32_t*)(Pb + (rxB * 72 + c) * 2) = pp[idx][1];
            }
            if (wc == 0 && (lane & 3) == 0) {
                float* scb = (float*)(smc + OFF_SC + (t & 1) * 128);
                scb[rxA] = scA;
                scb[rxB] = scB;
            }
            NBAR_ARRIVE(2 + (t & 1), 256);             // P(t) ready
        }
        if ((lane & 3) == 0) {
            ls[wc * 32 + rxA] = lA;
            ls[wc * 32 + rxB] = lB;
        }
        NBAR_SYNC(6, 256);   // ls visible to G2
        NBAR_SYNC(7, 256);   // G2's Ys writes done
    } else {
        // ================= G2: rescale + GEMM2 =================
        const int wq2 = w - 4;
        const int c0 = 2 * (lane & 3);
        const int r0 = lane >> 2;

        float y[2][8][4];
#pragma unroll
        for (int bd = 0; bd < 2; bd++)
#pragma unroll
            for (int i = 0; i < 8; i++)
#pragma unroll
                for (int j = 0; j < 4; j++) y[bd][i][j] = 0.f;

        for (int t = 0; t < 64; t++) {
            NBAR_SYNC(2 + (t & 1), 256);      // P(t), sc(t) ready
            const float* scb = (const float*)(smc + OFF_SC + (t & 1) * 128);
            float s0 = scb[r0], s1 = scb[r0 + 8], s2 = scb[r0 + 16], s3 = scb[r0 + 24];
            bool nor = (s0 == 1.f) & (s1 == 1.f) & (s2 == 1.f) & (s3 == 1.f);
            if (!__all_sync(0xffffffffu, nor)) {
#pragma unroll
                for (int i = 0; i < 8; i++) {
                    y[0][i][0] *= s0; y[0][i][1] *= s0;
                    y[0][i][2] *= s1; y[0][i][3] *= s1;
                    y[1][i][0] *= s2; y[1][i][1] *= s2;
                    y[1][i][2] *= s3; y[1][i][3] *= s3;
                }
            }
            MBAR_WAIT(((t & 1) ? barV1 : barV0), (t >> 1) & 1);
            const uint32_t bV = sb + OFF_V + (t & 1) * 32768;
            const uint32_t Pb = sb + OFF_P + (t & 1) * 4608;
#pragma unroll
            for (int kk = 0; kk < 4; kk++) {
                uint32_t pa0[4], pa1[4];
                int pr = (lane & 7) + ((lane & 8) ? 8 : 0);
                int pc = kk * 16 + ((lane & 16) ? 8 : 0);
                ldsm4(pa0, Pb + (pr * 72 + pc) * 2);
                ldsm4(pa1, Pb + ((pr + 16) * 72 + pc) * 2);
                int colb = kk * 32 + ((lane & 8) ? 16 : 0);
#pragma unroll
                for (int np = 0; np < 4; np++) {
                    int vrow = wq2 * 64 + np * 16 + (lane & 7) + ((lane & 16) ? 8 : 0);
                    uint32_t bv[4];
                    ldsm4(bv, bV + vrow * 128 + (colb ^ ((vrow & 7) << 4)));
                    mma16816(y[0][np*2],   pa0, bv);
                    mma16816(y[0][np*2+1], pa0, bv + 2);
                    mma16816(y[1][np*2],   pa1, bv);
                    mma16816(y[1][np*2+1], pa1, bv + 2);
                }
            }
            NBAR_SYNC(14, 128);               // all G2 done with V(t)/P(t)
            if (tid == 128 && t + 2 < 64) {
                uint32_t bv2 = (t & 1) ? barV1 : barV0;
                MBAR_EXPECT_TX(bv2, 32768);
                bulk_g2s(sb + OFF_V + (t & 1) * 32768, vt + (size_t)(t + 2) * 16384, 32768, bv2);
            }
            if (t < 62) NBAR_ARRIVE(8 + (t & 1), 256);   // P slot free
        }

        NBAR_SYNC(6, 256);   // ls visible
        float rl[4];
#pragma unroll
        for (int q = 0; q < 4; q++) {
            int r = r0 + q * 8;
            rl[q] = 1.f / (ls[r] + ls[32 + r]);
        }
        NBAR_SYNC(14, 128);  // all G2 read ls before Ys overwrite
        float* Ys = (float*)smc;   // [32][260] f32 (overlaps P/sc/mx/ls/rdt — all dead)
#pragma unroll
        for (int bd = 0; bd < 2; bd++)
#pragma unroll
            for (int nt = 0; nt < 8; nt++) {
                int c = wq2 * 64 + (nt >> 1) * 16 + (nt & 1) * 8 + c0;
                int rA = bd * 16 + r0, rB = rA + 8;
                Ys[rA * 260 + c]     = y[bd][nt][0] * rl[bd * 2];
                Ys[rA * 260 + c + 1] = y[bd][nt][1] * rl[bd * 2];
                Ys[rB * 260 + c]     = y[bd][nt][2] * rl[bd * 2 + 1];
                Ys[rB * 260 + c + 1] = y[bd][nt][3] * rl[bd * 2 + 1];
            }
        NBAR_SYNC(7, 256);   // Ys published
    }

    // ---- common epilogue: BN + ReLU + residual (Ys visible after bar 7)
    float* Ys = (float*)smc;
    const int n = tid & 31, cg = tid >> 5;
#pragma unroll 4
    for (int it = 0; it < 32; it++) {
        int c = it * 8 + cg;
        float inv = gamma[c] * rsqrtf(var[c] + 1e-5f);
        float add = fmaf(-mean[c], inv, beta[c]);
        size_t idx = ((size_t)b * C_ + c) * N_ + qb + n;
        float yv = Ys[n * 260 + c];
        out[idx] = fmaxf(fmaf(yv, inv, add), 0.f) + x[idx];
    }
}

// ---------------------------------------------------------------------------
extern "C" void kernel_launch(void* const* d_in, const int* in_sizes, int n_in,
                              void* d_out, int out_size)
{
    (void)in_sizes; (void)n_in; (void)out_size;
    const float* x     = (const float*)d_in[0];
    const float* wv    = (const float*)d_in[1];
    const float* wq    = (const float*)d_in[2];
    const float* wk    = (const float*)d_in[3];
    const float* gamma = (const float*)d_in[4];
    const float* beta  = (const float*)d_in[5];
    const float* mean  = (const float*)d_in[6];
    const float* var   = (const float*)d_in[7];
    float* out = (float*)d_out;

    cudaFuncSetAttribute(proj_kernel, cudaFuncAttributeMaxDynamicSharedMemorySize, PJ_SZ);
    proj_kernel<<<dim3(64, B_), 256, PJ_SZ>>>(x, wv, wq, wk);
    cudaFuncSetAttribute(attn_kernel, cudaFuncAttributeMaxDynamicSharedMemorySize, SMEM_SZ);
    attn_kernel<<<dim3(128, B_), 256, SMEM_SZ>>>(x, gamma, beta, mean, var, out);
}

// round 15
// speedup vs baseline: 1.1988x; 1.0954x over previous
#include <cuda_runtime.h>
#include <cuda_fp16.h>
#include <stdint.h>

#define B_ 4
#define C_ 256
#define N_ 4096

// ---------------- device scratch (swizzled tile layouts, attn-ready) --------
__device__ __align__(256) __half g_qt [(size_t)B_ * 64 * 4096]; // 8KB q-tiles [r][qh32|ql32] sw128
__device__ __align__(256) __half g_kt [(size_t)B_ * 64 * 4096]; // 8KB k-tiles
__device__ __align__(256) __half g_vt [(size_t)B_ * 64 * 16384];// 32KB V^T tiles [c][n] sw128

// ---------------- asm helpers ----------------
__device__ __forceinline__ uint32_t smem_u32(const void* p) {
    uint32_t a;
    asm("{ .reg .u64 t; cvta.to.shared.u64 t, %1; cvt.u32.u64 %0, t; }" : "=r"(a) : "l"(p));
    return a;
}
__device__ __forceinline__ void ldsm4(uint32_t* r, uint32_t a) {
    asm volatile("ldmatrix.sync.aligned.m8n8.x4.shared.b16 {%0,%1,%2,%3}, [%4];"
        : "=r"(r[0]), "=r"(r[1]), "=r"(r[2]), "=r"(r[3]) : "r"(a));
}
__device__ __forceinline__ void mma16816(float* c, const uint32_t* a, const uint32_t* b) {
    asm volatile("mma.sync.aligned.m16n8k16.row.col.f32.f16.f16.f32 "
        "{%0,%1,%2,%3}, {%4,%5,%6,%7}, {%8,%9}, {%0,%1,%2,%3};"
        : "+f"(c[0]), "+f"(c[1]), "+f"(c[2]), "+f"(c[3])
        : "r"(a[0]), "r"(a[1]), "r"(a[2]), "r"(a[3]), "r"(b[0]), "r"(b[1]));
}
__device__ __forceinline__ uint32_t pk(float lo, float hi) {
    uint32_t r;
    asm("cvt.rn.f16x2.f32 %0, %1, %2;" : "=r"(r) : "f"(hi), "f"(lo));
    return r;
}
#define MBAR_INIT(m, c) \
    asm volatile("mbarrier.init.shared.b64 [%0], %1;" :: "r"((uint32_t)(m)), "r"((uint32_t)(c)) : "memory")
#define MBAR_EXPECT_TX(m, b) \
    asm volatile("mbarrier.arrive.expect_tx.shared.b64 _, [%0], %1;" :: "r"((uint32_t)(m)), "r"((uint32_t)(b)) : "memory")
#define MBAR_WAIT(m, ph) do { \
    uint32_t _m = (uint32_t)(m), _p = (uint32_t)(ph), _d; \
    asm volatile("{\n\t.reg .pred p;\n\t" \
        "mbarrier.try_wait.parity.acquire.cta.shared::cta.b64 p, [%1], %2;\n\tselp.b32 %0,1,0,p;\n\t}" \
        : "=r"(_d) : "r"(_m), "r"(_p) : "memory"); \
    if (!_d) { asm volatile("{\n\t.reg .pred P1;\n\tWL_%=:\n\t" \
        "mbarrier.try_wait.parity.acquire.cta.shared::cta.b64 P1, [%0], %1, 0x989680;\n\t" \
        "@P1 bra.uni WD_%=;\n\tbra.uni WL_%=;\n\tWD_%=:\n\t}" :: "r"(_m), "r"(_p) : "memory"); } \
} while (0)
__device__ __forceinline__ void bulk_g2s(uint32_t dst, const void* src, uint32_t bytes, uint32_t mbar) {
    asm volatile("cp.async.bulk.shared::cluster.global.mbarrier::complete_tx::bytes [%0], [%1], %2, [%3];"
        :: "r"(dst), "l"(__cvta_generic_to_global(src)), "r"(bytes), "r"(mbar) : "memory");
}
#define NBAR_SYNC(id, cnt)   asm volatile("bar.sync %0, %1;"   :: "r"(id), "r"(cnt) : "memory")
#define NBAR_ARRIVE(id, cnt) asm volatile("bar.arrive %0, %1;" :: "r"(id), "r"(cnt) : "memory")

// ---------------------------------------------------------------------------
// Kernel 1: UNIFIED HMMA projection (unchanged from R14 — proj ~22us).
// ---------------------------------------------------------------------------
#define PJ_WV   0
#define PJ_WQH  32768
#define PJ_WQL  40960
#define PJ_X32  49152
#define PJ_XH   66560
#define PJ_XL   75776
#define PJ_SZ   84992

__global__ __launch_bounds__(256, 2) void proj_kernel(
    const float* __restrict__ x, const float* __restrict__ wv,
    const float* __restrict__ wq, const float* __restrict__ wk)
{
    extern __shared__ char smc[];
    float* xs32 = (float*)(smc + PJ_X32);
    const uint32_t sb = smem_u32(smc);
    const int tid = threadIdx.x, w = tid >> 5, lane = tid & 31;
    const int wn = w & 3, wj = w >> 2;
    const int b = blockIdx.y, n0 = blockIdx.x * 64;

    float accV[16][4];
    float accQ[4][4];
#pragma unroll
    for (int i = 0; i < 16; i++)
#pragma unroll
        for (int j = 0; j < 4; j++) accV[i][j] = 0.f;
#pragma unroll
    for (int i = 0; i < 4; i++)
#pragma unroll
        for (int j = 0; j < 4; j++) accQ[i][j] = 0.f;

    for (int c0 = 0; c0 < 256; c0 += 64) {
        __syncthreads();
#pragma unroll
        for (int it = 0; it < 16; it++) {
            int f4 = tid + it * 256;
            int jl = f4 >> 4, c4 = f4 & 15;
            float4 v = *(const float4*)(wv + (size_t)jl * 256 + c0 + c4 * 4);
            __half h[4];
            h[0] = __float2half_rn(v.x); h[1] = __float2half_rn(v.y);
            h[2] = __float2half_rn(v.z); h[3] = __float2half_rn(v.w);
            *(uint2*)(smc + PJ_WV + jl * 128 + ((c4 * 8) ^ ((jl & 7) << 4))) = *(uint2*)h;
        }
#pragma unroll
        for (int it = 0; it < 4; it++) {
            int f4 = tid + it * 256;
            int jl = f4 >> 4, c4 = f4 & 15;
            const float* src = ((jl < 32) ? (wq + (size_t)jl * 256)
                                          : (wk + (size_t)(jl - 32) * 256)) + c0 + c4 * 4;
            float4 v = *(const float4*)src;
            __half h[4], l[4];
            h[0] = __float2half_rn(v.x); h[1] = __float2half_rn(v.y);
            h[2] = __float2half_rn(v.z); h[3] = __float2half_rn(v.w);
            l[0] = __float2half_rn(v.x - __half2float(h[0]));
            l[1] = __float2half_rn(v.y - __half2float(h[1]));
            l[2] = __float2half_rn(v.z - __half2float(h[2]));
            l[3] = __float2half_rn(v.w - __half2float(h[3]));
            *(uint2*)(smc + PJ_WQH + jl * 128 + ((c4 * 8) ^ ((jl & 7) << 4))) = *(uint2*)h;
            *(uint2*)(smc + PJ_WQL + jl * 128 + ((c4 * 8) ^ ((jl & 7) << 4))) = *(uint2*)l;
        }
#pragma unroll
        for (int it = 0; it < 4; it++) {
            int f4 = tid + it * 256;
            int cl = f4 >> 4, n4 = f4 & 15;
            float4 v = *(const float4*)(x + (size_t)(b * 256 + c0 + cl) * 4096 + n0 + n4 * 4);
            *(float4*)(xs32 + cl * 68 + n4 * 4) = v;
        }
        __syncthreads();
        {
            int n = tid & 63, cq = tid >> 6;
#pragma unroll
            for (int i = 0; i < 4; i++) {
                int c = cq * 16 + i * 4;
                __half h[4], l[4];
#pragma unroll
                for (int k2 = 0; k2 < 4; k2++) {
                    float f = xs32[(c + k2) * 68 + n];
                    h[k2] = __float2half_rn(f);
                    l[k2] = __float2half_rn(f - __half2float(h[k2]));
                }
                *(uint2*)(smc + PJ_XH + n * 144 + c * 2) = *(uint2*)h;
                *(uint2*)(smc + PJ_XL + n * 144 + c * 2) = *(uint2*)l;
            }
        }
        __syncthreads();
#pragma unroll
        for (int kk = 0; kk < 4; kk++) {
            uint32_t ah[4], al[4];
            int arow = wn * 16 + (lane & 7) + ((lane & 8) ? 8 : 0);
            int aoff = arow * 144 + kk * 32 + ((lane & 16) ? 16 : 0);
            ldsm4(ah, sb + PJ_XH + aoff);
            ldsm4(al, sb + PJ_XL + aoff);
            int bcol = kk * 32 + ((lane & 8) ? 16 : 0);
            int jrb = (lane & 7) + ((lane & 16) ? 8 : 0);
#pragma unroll
            for (int jp = 0; jp < 8; jp++) {
                int jrow = wj * 128 + jp * 16 + jrb;
                uint32_t bh[4];
                ldsm4(bh, sb + PJ_WV + jrow * 128 + (bcol ^ ((jrow & 7) << 4)));
                mma16816(accV[jp*2],   ah, bh);
                mma16816(accV[jp*2+1], ah, bh + 2);
            }
#pragma unroll
            for (int jq = 0; jq < 2; jq++) {
                int jrow = wj * 32 + jq * 16 + jrb;
                uint32_t bh[4], bl[4];
                ldsm4(bh, sb + PJ_WQH + jrow * 128 + (bcol ^ ((jrow & 7) << 4)));
                ldsm4(bl, sb + PJ_WQL + jrow * 128 + (bcol ^ ((jrow & 7) << 4)));
                mma16816(accQ[jq*2],   ah, bh);
                mma16816(accQ[jq*2+1], ah, bh + 2);
                mma16816(accQ[jq*2],   al, bh);
                mma16816(accQ[jq*2+1], al, bh + 2);
                mma16816(accQ[jq*2],   ah, bl);
                mma16816(accQ[jq*2+1], ah, bl + 2);
            }
        }
    }

    const int rA = wn * 16 + (lane >> 2), rB = rA + 8;
    const int c0l = 2 * (lane & 3);

#pragma unroll
    for (int t = 0; t < 4; t++) {
        int j = wj * 32 + (t >> 1) * 16 + (t & 1) * 8 + c0l;
        bool isQ = j < 32;
        int qc = isQ ? j : j - 32;
        char* tb = (char*)((isQ ? g_qt : g_kt) + ((size_t)(b * 64 + blockIdx.x)) * 4096);
#pragma unroll
        for (int rr = 0; rr < 2; rr++) {
            int r = rr ? rB : rA;
            float v0 = accQ[t][rr * 2], v1 = accQ[t][rr * 2 + 1];
            __half h0 = __float2half_rn(v0), h1 = __float2half_rn(v1);
            __half l0 = __float2half_rn(v0 - __half2float(h0));
            __half l1 = __float2half_rn(v1 - __half2float(h1));
            uint32_t hp = (uint32_t)*(uint16_t*)&h0 | ((uint32_t)*(uint16_t*)&h1 << 16);
            uint32_t lp = (uint32_t)*(uint16_t*)&l0 | ((uint32_t)*(uint16_t*)&l1 << 16);
            *(uint32_t*)(tb + r * 128 + ((qc * 2)      ^ ((r & 7) << 4))) = hp;
            *(uint32_t*)(tb + r * 128 + ((64 + qc * 2) ^ ((r & 7) << 4))) = lp;
        }
    }

    __syncthreads();
    __half* st = (__half*)smc;
#pragma unroll
    for (int jp = 0; jp < 8; jp++)
#pragma unroll
        for (int h = 0; h < 2; h++) {
            int j = wj * 128 + jp * 16 + h * 8 + c0l;
            st[j * 72 + rA]       = __float2half_rn(accV[jp*2+h][0]);
            st[(j + 1) * 72 + rA] = __float2half_rn(accV[jp*2+h][1]);
            st[j * 72 + rB]       = __float2half_rn(accV[jp*2+h][2]);
            st[(j + 1) * 72 + rB] = __float2half_rn(accV[jp*2+h][3]);
        }
    __syncthreads();
    {
        char* tb = (char*)(g_vt + ((size_t)(b * 64 + blockIdx.x)) * 16384);
        int c = tid;
#pragma unroll
        for (int hh = 0; hh < 8; hh++) {
            int nl = hh * 8;
            uint4 v = *(uint4*)(st + c * 72 + nl);
            *(uint4*)(tb + c * 128 + ((nl * 2) ^ ((c & 7) << 4))) = v;
        }
    }
}

// ---------------------------------------------------------------------------
// Kernel 2: warp-specialized HMMA flash attention (R11 protocol).
// GEMM1 is now 2-pass: S = Qh*Kh + Ql*Kh  (K-lo pass dropped; kl never loaded).
// ---------------------------------------------------------------------------
#define OFF_P   0          /* 2 x 4608 (slot0 head doubles as 4KB Q staging) */
#define OFF_SC  9216       /* 2 x 32 f32 */
#define OFF_MX  9472       /* 2 x 2 x 32 f32 */
#define OFF_LS  9984       /* 2 x 32 f32 */
#define OFF_RDT 10240      /* 16384 */
#define OFF_K   26624      /* 2 x 8192 */
#define OFF_V   43008      /* 2 x 32768 */
#define OFF_BAR 108544
#define SMEM_SZ 108608

__global__ __launch_bounds__(256, 2) void attn_kernel(
    const float* __restrict__ x, const float* __restrict__ gamma,
    const float* __restrict__ beta, const float* __restrict__ mean,
    const float* __restrict__ var, float* __restrict__ out)
{
    extern __shared__ char smc[];
    float* rdt = (float*)(smc + OFF_RDT);
    float* ls  = (float*)(smc + OFF_LS);
    const uint32_t sb = smem_u32(smc);
    const uint32_t barK0 = sb + OFF_BAR, barK1 = sb + OFF_BAR + 8;
    const uint32_t barV0 = sb + OFF_BAR + 16, barV1 = sb + OFF_BAR + 24;
    const int tid = threadIdx.x, w = tid >> 5, lane = tid & 31;
    const int b = blockIdx.y, qt = blockIdx.x, qb = qt * 32;

    for (int i = tid; i < 4096; i += 256) {
        int dy = i >> 6, dx = i & 63;
        rdt[i] = 1.0f / (sqrtf((float)(dy * dy + dx * dx)) + 1.0f);
    }
    if (tid == 0) {
        MBAR_INIT(barK0, 1); MBAR_INIT(barK1, 1);
        MBAR_INIT(barV0, 1); MBAR_INIT(barV1, 1);
    }
    {   // Q staging into P slot0 head (4KB); consumed into regs before t=0 writes
        const char* qsrc = (const char*)(g_qt + ((size_t)(b * 64 + (qt >> 1))) * 4096)
                         + (size_t)(qt & 1) * 32 * 128;
        ((uint4*)smc)[tid] = ((const uint4*)qsrc)[tid];
    }
    __syncthreads();

    const __half* kt = g_kt + (size_t)b * 64 * 4096;
    const __half* vt = g_vt + (size_t)b * 64 * 16384;
    if (tid == 0) {   // prologue: K(0),K(1),V(0),V(1)
        MBAR_EXPECT_TX(barK0, 8192);  bulk_g2s(sb + OFF_K, kt, 8192, barK0);
        MBAR_EXPECT_TX(barK1, 8192);  bulk_g2s(sb + OFF_K + 8192, kt + 4096, 8192, barK1);
        MBAR_EXPECT_TX(barV0, 32768); bulk_g2s(sb + OFF_V, vt, 32768, barV0);
        MBAR_EXPECT_TX(barV1, 32768); bulk_g2s(sb + OFF_V + 32768, vt + 16384, 32768, barV1);
    }

    if (w < 4) {
        // ================= G1: GEMM1 + softmax =================
        const int wm = w & 1, wc = w >> 1;
        const int rxA = wm * 16 + (lane >> 2), rxB = rxA + 8;
        const int c0 = 2 * (lane & 3);
        const int rxAi = (qt & 1) * 32 + rxA, rxBi = rxAi + 8;
        const int ry = qt >> 1;

        uint32_t qf[2][2][4];
#pragma unroll
        for (int hl = 0; hl < 2; hl++)
#pragma unroll
            for (int kk = 0; kk < 2; kk++) {
                int row = wm * 16 + (lane & 7) + ((lane & 8) ? 8 : 0);
                int colb = hl * 64 + kk * 32 + ((lane & 16) ? 16 : 0);
                ldsm4(qf[hl][kk], sb + row * 128 + (colb ^ ((row & 7) << 4)));
            }
        NBAR_SYNC(1, 128);   // all G1 qf reads done before P slot0 writes at t=0

        float mA = -1e30f, mB = -1e30f, lA = 0.f, lB = 0.f;

        for (int t = 0; t < 64; t++) {
            MBAR_WAIT(((t & 1) ? barK1 : barK0), (t >> 1) & 1);
            const uint32_t bK = sb + OFF_K + (t & 1) * 8192;

            // GEMM1 (2-pass): S = Qh*Kh + Ql*Kh   (16 HMMA, 4 LDSM)
            float s[4][4];
#pragma unroll
            for (int i = 0; i < 4; i++)
#pragma unroll
                for (int j = 0; j < 4; j++) s[i][j] = 0.f;
#pragma unroll
            for (int kk = 0; kk < 2; kk++) {
                int colb = kk * 32 + ((lane & 8) ? 16 : 0);
                int kr0 = wc * 32 + (lane & 7) + ((lane & 16) ? 8 : 0);
                uint32_t bh0[4], bh1[4];
                ldsm4(bh0, bK + kr0 * 128 + (colb ^ ((kr0 & 7) << 4)));
                int kr1 = kr0 + 16;
                ldsm4(bh1, bK + kr1 * 128 + (colb ^ ((kr1 & 7) << 4)));
                mma16816(s[0], qf[0][kk], bh0);
                mma16816(s[1], qf[0][kk], bh0 + 2);
                mma16816(s[2], qf[0][kk], bh1);
                mma16816(s[3], qf[0][kk], bh1 + 2);
                mma16816(s[0], qf[1][kk], bh0);
                mma16816(s[1], qf[1][kk], bh0 + 2);
                mma16816(s[2], qf[1][kk], bh1);
                mma16816(s[3], qf[1][kk], bh1 + 2);
            }

            const float* rdtp = rdt + ((ry > t) ? (ry - t) : (t - ry)) * 64;
            float tmA = -1e30f, tmB = -1e30f;
#pragma unroll
            for (int idx = 0; idx < 4; idx++) {
                int c = wc * 32 + (idx >> 1) * 16 + (idx & 1) * 8 + c0;
                int d0 = rxAi - c;     d0 = d0 < 0 ? -d0 : d0;
                int d1 = rxAi - c - 1; d1 = d1 < 0 ? -d1 : d1;
                int d2 = rxBi - c;     d2 = d2 < 0 ? -d2 : d2;
                int d3 = rxBi - c - 1; d3 = d3 < 0 ? -d3 : d3;
                s[idx][0] *= rdtp[d0];
                s[idx][1] *= rdtp[d1];
                s[idx][2] *= rdtp[d2];
                s[idx][3] *= rdtp[d3];
                tmA = fmaxf(tmA, fmaxf(s[idx][0], s[idx][1]));
                tmB = fmaxf(tmB, fmaxf(s[idx][2], s[idx][3]));
            }
            tmA = fmaxf(tmA, __shfl_xor_sync(0xffffffffu, tmA, 1));
            tmA = fmaxf(tmA, __shfl_xor_sync(0xffffffffu, tmA, 2));
            tmB = fmaxf(tmB, __shfl_xor_sync(0xffffffffu, tmB, 1));
            tmB = fmaxf(tmB, __shfl_xor_sync(0xffffffffu, tmB, 2));
            float* mxs = (float*)(smc + OFF_MX + (t & 1) * 256);
            if ((lane & 3) == 0) {
                mxs[wc * 32 + rxA] = tmA;
                mxs[wc * 32 + rxB] = tmB;
            }
            NBAR_SYNC(1, 128);
            if (tid == 0 && t + 2 < 64) {
                uint32_t bk = (t & 1) ? barK1 : barK0;
                MBAR_EXPECT_TX(bk, 8192);
                bulk_g2s(sb + OFF_K + (t & 1) * 8192, kt + (size_t)(t + 2) * 4096, 8192, bk);
            }
            float gmA = fmaxf(mxs[rxA], mxs[32 + rxA]);
            float gmB = fmaxf(mxs[rxB], mxs[32 + rxB]);
            float mnA = fmaxf(mA, gmA), mnB = fmaxf(mB, gmB);
            float scA = __expf(mA - mnA), scB = __expf(mB - mnB);
            mA = mnA; mB = mnB;

            float sumA = 0.f, sumB = 0.f;
            uint32_t pp[4][2];
#pragma unroll
            for (int idx = 0; idx < 4; idx++) {
                float p0 = __expf(s[idx][0] - mnA), p1 = __expf(s[idx][1] - mnA);
                float p2 = __expf(s[idx][2] - mnB), p3 = __expf(s[idx][3] - mnB);
                sumA += p0 + p1; sumB += p2 + p3;
                pp[idx][0] = pk(p0, p1);
                pp[idx][1] = pk(p2, p3);
            }
            sumA += __shfl_xor_sync(0xffffffffu, sumA, 1);
            sumA += __shfl_xor_sync(0xffffffffu, sumA, 2);
            sumB += __shfl_xor_sync(0xffffffffu, sumB, 1);
            sumB += __shfl_xor_sync(0xffffffffu, sumB, 2);
            lA = lA * scA + sumA;
            lB = lB * scB + sumB;

            if (t >= 2) NBAR_SYNC(8 + (t & 1), 256);   // slot free (G2 done t-2)
            char* Pb = smc + OFF_P + (t & 1) * 4608;
#pragma unroll
            for (int idx = 0; idx < 4; idx++) {
                int c = wc * 32 + (idx >> 1) * 16 + (idx & 1) * 8 + c0;
                *(uint32_t*)(Pb + (rxA * 72 + c) * 2) = pp[idx][0];
                *(uint32_t*)(Pb + (rxB * 72 + c) * 2) = pp[idx][1];
            }
            if (wc == 0 && (lane & 3) == 0) {
                float* scb = (float*)(smc + OFF_SC + (t & 1) * 128);
                scb[rxA] = scA;
                scb[rxB] = scB;
            }
            NBAR_ARRIVE(2 + (t & 1), 256);             // P(t) ready
        }
        if ((lane & 3) == 0) {
            ls[wc * 32 + rxA] = lA;
            ls[wc * 32 + rxB] = lB;
        }
        NBAR_SYNC(6, 256);   // ls visible to G2
        NBAR_SYNC(7, 256);   // G2's Ys writes done
    } else {
        // ================= G2: rescale + GEMM2 =================
        const int wq2 = w - 4;
        const int c0 = 2 * (lane & 3);
        const int r0 = lane >> 2;

        float y[2][8][4];
#pragma unroll
        for (int bd = 0; bd < 2; bd++)
#pragma unroll
            for (int i = 0; i < 8; i++)
#pragma unroll
                for (int j = 0; j < 4; j++) y[bd][i][j] = 0.f;

        for (int t = 0; t < 64; t++) {
            NBAR_SYNC(2 + (t & 1), 256);      // P(t), sc(t) ready
            const float* scb = (const float*)(smc + OFF_SC + (t & 1) * 128);
            float s0 = scb[r0], s1 = scb[r0 + 8], s2 = scb[r0 + 16], s3 = scb[r0 + 24];
            bool nor = (s0 == 1.f) & (s1 == 1.f) & (s2 == 1.f) & (s3 == 1.f);
            if (!__all_sync(0xffffffffu, nor)) {
#pragma unroll
                for (int i = 0; i < 8; i++) {
                    y[0][i][0] *= s0; y[0][i][1] *= s0;
                    y[0][i][2] *= s1; y[0][i][3] *= s1;
                    y[1][i][0] *= s2; y[1][i][1] *= s2;
                    y[1][i][2] *= s3; y[1][i][3] *= s3;
                }
            }
            MBAR_WAIT(((t & 1) ? barV1 : barV0), (t >> 1) & 1);
            const uint32_t bV = sb + OFF_V + (t & 1) * 32768;
            const uint32_t Pb = sb + OFF_P + (t & 1) * 4608;
#pragma unroll
            for (int kk = 0; kk < 4; kk++) {
                uint32_t pa0[4], pa1[4];
                int pr = (lane & 7) + ((lane & 8) ? 8 : 0);
                int pc = kk * 16 + ((lane & 16) ? 8 : 0);
                ldsm4(pa0, Pb + (pr * 72 + pc) * 2);
                ldsm4(pa1, Pb + ((pr + 16) * 72 + pc) * 2);
                int colb = kk * 32 + ((lane & 8) ? 16 : 0);
#pragma unroll
                for (int np = 0; np < 4; np++) {
                    int vrow = wq2 * 64 + np * 16 + (lane & 7) + ((lane & 16) ? 8 : 0);
                    uint32_t bv[4];
                    ldsm4(bv, bV + vrow * 128 + (colb ^ ((vrow & 7) << 4)));
                    mma16816(y[0][np*2],   pa0, bv);
                    mma16816(y[0][np*2+1], pa0, bv + 2);
                    mma16816(y[1][np*2],   pa1, bv);
                    mma16816(y[1][np*2+1], pa1, bv + 2);
                }
            }
            NBAR_SYNC(14, 128);               // all G2 done with V(t)/P(t)
            if (tid == 128 && t + 2 < 64) {
                uint32_t bv2 = (t & 1) ? barV1 : barV0;
                MBAR_EXPECT_TX(bv2, 32768);
                bulk_g2s(sb + OFF_V + (t & 1) * 32768, vt + (size_t)(t + 2) * 16384, 32768, bv2);
            }
            if (t < 62) NBAR_ARRIVE(8 + (t & 1), 256);   // P slot free
        }

        NBAR_SYNC(6, 256);   // ls visible
        float rl[4];
#pragma unroll
        for (int q = 0; q < 4; q++) {
            int r = r0 + q * 8;
            rl[q] = 1.f / (ls[r] + ls[32 + r]);
        }
        NBAR_SYNC(14, 128);  // all G2 read ls before Ys overwrite
        float* Ys = (float*)smc;   // [32][260] f32 (overlaps P/sc/mx/ls/rdt — all dead)
#pragma unroll
        for (int bd = 0; bd < 2; bd++)
#pragma unroll
            for (int nt = 0; nt < 8; nt++) {
                int c = wq2 * 64 + (nt >> 1) * 16 + (nt & 1) * 8 + c0;
                int rA = bd * 16 + r0, rB = rA + 8;
                Ys[rA * 260 + c]     = y[bd][nt][0] * rl[bd * 2];
                Ys[rA * 260 + c + 1] = y[bd][nt][1] * rl[bd * 2];
                Ys[rB * 260 + c]     = y[bd][nt][2] * rl[bd * 2 + 1];
                Ys[rB * 260 + c + 1] = y[bd][nt][3] * rl[bd * 2 + 1];
            }
        NBAR_SYNC(7, 256);   // Ys published
    }

    // ---- common epilogue: BN + ReLU + residual (Ys visible after bar 7)
    float* Ys = (float*)smc;
    const int n = tid & 31, cg = tid >> 5;
#pragma unroll 4
    for (int it = 0; it < 32; it++) {
        int c = it * 8 + cg;
        float inv = gamma[c] * rsqrtf(var[c] + 1e-5f);
        float add = fmaf(-mean[c], inv, beta[c]);
        size_t idx = ((size_t)b * C_ + c) * N_ + qb + n;
        float yv = Ys[n * 260 + c];
        out[idx] = fmaxf(fmaf(yv, inv, add), 0.f) + x[idx];
    }
}

// ---------------------------------------------------------------------------
extern "C" void kernel_launch(void* const* d_in, const int* in_sizes, int n_in,
                              void* d_out, int out_size)
{
    (void)in_sizes; (void)n_in; (void)out_size;
    const float* x     = (const float*)d_in[0];
    const float* wv    = (const float*)d_in[1];
    const float* wq    = (const float*)d_in[2];
    const float* wk    = (const float*)d_in[3];
    const float* gamma = (const float*)d_in[4];
    const float* beta  = (const float*)d_in[5];
    const float* mean  = (const float*)d_in[6];
    const float* var   = (const float*)d_in[7];
    float* out = (float*)d_out;

    cudaFuncSetAttribute(proj_kernel, cudaFuncAttributeMaxDynamicSharedMemorySize, PJ_SZ);
    proj_kernel<<<dim3(64, B_), 256, PJ_SZ>>>(x, wv, wq, wk);
    cudaFuncSetAttribute(attn_kernel, cudaFuncAttributeMaxDynamicSharedMemorySize, SMEM_SZ);
    attn_kernel<<<dim3(128, B_), 256, SMEM_SZ>>>(x, gamma, beta, mean, var, out);
}